// round 4
// baseline (speedup 1.0000x reference)
#include <cuda_runtime.h>

#define Bb 32
#define Nn 128
#define Dd 64
#define Ee 5
#define T_ITERS 6
#define JSPLIT 8
#define JT 16      // Nn / JSPLIT
#define ROWS 16    // node rows per A block

__device__ float g_msg[Bb*Nn*Ee*Dd];            // 5.24 MB
__device__ float g_row[Bb*Nn*Ee];
__device__ float g_colba[Bb*Nn*Ee];
__device__ float g_part[JSPLIT][Bb*Nn][Dd];     // 8 MB
__device__ float g_prop[Bb*Nn*Dd];

typedef unsigned long long u64;

__device__ __forceinline__ u64 pack2(float a, float b) {
    u64 r; asm("mov.b64 %0, {%1,%2};" : "=l"(r) : "f"(a), "f"(b)); return r;
}
__device__ __forceinline__ void unpack2(u64 v, float& a, float& b) {
    float x, y; asm("mov.b64 {%0,%1}, %2;" : "=f"(x), "=f"(y) : "l"(v));
    a = x; b = y;
}
__device__ __forceinline__ u64 fma2(u64 a, u64 b, u64 c) {
    u64 d; asm("fma.rn.f32x2 %0, %1, %2, %3;" : "=l"(d) : "l"(a), "l"(b), "l"(c)); return d;
}
__device__ __forceinline__ float sig(float x) {
    return 1.0f / (1.0f + __expf(-x));
}

__device__ __forceinline__ unsigned cvta_smem(const void* p) {
    return (unsigned)__cvta_generic_to_shared(p);
}
__device__ __forceinline__ void cpa16(unsigned dst, const void* src) {
    asm volatile("cp.async.ca.shared.global [%0], [%1], 16;\n" :: "r"(dst), "l"(src));
}
#define CP_COMMIT asm volatile("cp.async.commit_group;\n" ::: "memory")
#define CP_WAIT0  asm volatile("cp.async.wait_group 0;\n" ::: "memory")

// ---------------------------------------------------------------------------
// Kernel A: (t>0) GRU update (merged = sum of 8 partials) -> new prop,
//           then msg = prop @ We + be, row/col reductions.
// grid 256 (16 rows each), 128 threads: (n = t>>3, fg = t&7, 8-wide f/d tile)
// smem: one 80KB weight region reused: [Wr|Wz] -> [Wh|We(2:5)] -> [We(0:2)...]
// ---------------------------------------------------------------------------
extern "C" __global__ void __launch_bounds__(128)
kA(int titer, const float* __restrict__ inputs,
   const float* __restrict__ We, const float* __restrict__ be,
   const float* __restrict__ Wa, const float* __restrict__ ba,
   const float* __restrict__ Wr, const float* __restrict__ br,
   const float* __restrict__ Wz, const float* __restrict__ bz,
   const float* __restrict__ Wh, const float* __restrict__ bh)
{
    extern __shared__ float sm[];
    float* sW  = sm;                    // 20480 floats (80 KB)
    float* sa  = sm + 20480;            // [16][132]  merged | prop_old
    float* sp  = sa + ROWS*132;         // [16][68]   new prop
    float* sh2 = sp + ROWS*68;          // [16][68]   r * prop
    float* sWa = sh2 + ROWS*68;         // [5][128]

    const int r0 = blockIdx.x * ROWS;
    const int t  = threadIdx.x;
    const int n  = t >> 3;
    const int fg = t & 7;
    const int f0 = fg * 8;
    const unsigned sWaddr  = cvta_smem(sW);
    const unsigned sWaaddr = cvta_smem(sWa);

    if (titer > 0) {
        // prop from iteration t-1: at t==1 that is exactly `inputs`
        // (g_prop is only written for t>=1; never trust cross-run state).
        const float* pold = (titer == 1) ? inputs : (const float*)g_prop;

        // stage Wr -> sW[0:8192], Wz -> sW[8192:16384] (async)
        for (int i = t; i < 2048; i += 128) {
            cpa16(sWaddr + i*16, Wr + 4*i);
            cpa16(sWaddr + 8192*4 + i*16, Wz + 4*i);
        }
        CP_COMMIT;
        // merged = sum of 8 partials; sa = [merged | prop_old]
        {
            const float* pb = &g_part[0][r0 + n][f0];
            float4 s0 = make_float4(0.f,0.f,0.f,0.f), s1 = s0;
#pragma unroll
            for (int p = 0; p < JSPLIT; p++) {
                const float4* q = (const float4*)(pb + (size_t)p * (Bb*Nn*Dd));
                float4 a = q[0], c = q[1];
                s0.x += a.x; s0.y += a.y; s0.z += a.z; s0.w += a.w;
                s1.x += c.x; s1.y += c.y; s1.z += c.z; s1.w += c.w;
            }
            *(float4*)&sa[n*132 + f0]     = s0;
            *(float4*)&sa[n*132 + f0 + 4] = s1;
            const float4* pr = (const float4*)&pold[(size_t)(r0 + n)*Dd + f0];
            *(float4*)&sa[n*132 + 64 + f0]     = pr[0];
            *(float4*)&sa[n*132 + 64 + f0 + 4] = pr[1];
        }
        CP_WAIT0;
        __syncthreads();

        // r, z gates
        float4 br0 = *(const float4*)&br[f0], br1 = *(const float4*)&br[f0+4];
        float4 bz0 = *(const float4*)&bz[f0], bz1 = *(const float4*)&bz[f0+4];
        u64 accr[4] = {pack2(br0.x,br0.y), pack2(br0.z,br0.w),
                       pack2(br1.x,br1.y), pack2(br1.z,br1.w)};
        u64 accz[4] = {pack2(bz0.x,bz0.y), pack2(bz0.z,bz0.w),
                       pack2(bz1.x,bz1.y), pack2(bz1.z,bz1.w)};
#pragma unroll 4
        for (int k = 0; k < 128; k++) {
            float a = sa[n*132 + k];
            u64 aa = pack2(a, a);
            float4 w0 = *(const float4*)&sW[k*64 + f0];
            float4 w1 = *(const float4*)&sW[k*64 + f0 + 4];
            float4 z0 = *(const float4*)&sW[8192 + k*64 + f0];
            float4 z1 = *(const float4*)&sW[8192 + k*64 + f0 + 4];
            accr[0] = fma2(aa, pack2(w0.x,w0.y), accr[0]);
            accr[1] = fma2(aa, pack2(w0.z,w0.w), accr[1]);
            accr[2] = fma2(aa, pack2(w1.x,w1.y), accr[2]);
            accr[3] = fma2(aa, pack2(w1.z,w1.w), accr[3]);
            accz[0] = fma2(aa, pack2(z0.x,z0.y), accz[0]);
            accz[1] = fma2(aa, pack2(z0.z,z0.w), accz[1]);
            accz[2] = fma2(aa, pack2(z1.x,z1.y), accz[2]);
            accz[3] = fma2(aa, pack2(z1.z,z1.w), accz[3]);
        }
        float rv[8], zv[8], zq[8];
        unpack2(accr[0], rv[0], rv[1]); unpack2(accr[1], rv[2], rv[3]);
        unpack2(accr[2], rv[4], rv[5]); unpack2(accr[3], rv[6], rv[7]);
        unpack2(accz[0], zv[0], zv[1]); unpack2(accz[1], zv[2], zv[3]);
        unpack2(accz[2], zv[4], zv[5]); unpack2(accz[3], zv[6], zv[7]);
#pragma unroll
        for (int u = 0; u < 8; u++) {
            float rg = sig(rv[u]);
            zq[u] = sig(zv[u]);
            sh2[n*68 + f0 + u] = rg * sa[n*132 + 64 + f0 + u];
        }
        __syncthreads();   // everyone done with Wr/Wz
        // stage Wh -> sW[0:8192]; We experts 2..4 -> sW[8192:20480]
        for (int i = t; i < 2048; i += 128) cpa16(sWaddr + i*16, Wh + 4*i);
        for (int i = t; i < 3072; i += 128) cpa16(sWaddr + 8192*4 + i*16, We + 8192 + 4*i);
        CP_COMMIT; CP_WAIT0;
        __syncthreads();

        // h gate
        float4 bh0 = *(const float4*)&bh[f0], bh1 = *(const float4*)&bh[f0+4];
        u64 acch[4] = {pack2(bh0.x,bh0.y), pack2(bh0.z,bh0.w),
                       pack2(bh1.x,bh1.y), pack2(bh1.z,bh1.w)};
#pragma unroll 4
        for (int k = 0; k < 64; k++) {
            float a = sa[n*132 + k];
            u64 aa = pack2(a, a);
            float4 w0 = *(const float4*)&sW[k*64 + f0];
            float4 w1 = *(const float4*)&sW[k*64 + f0 + 4];
            acch[0] = fma2(aa, pack2(w0.x,w0.y), acch[0]);
            acch[1] = fma2(aa, pack2(w0.z,w0.w), acch[1]);
            acch[2] = fma2(aa, pack2(w1.x,w1.y), acch[2]);
            acch[3] = fma2(aa, pack2(w1.z,w1.w), acch[3]);
        }
#pragma unroll 4
        for (int k = 0; k < 64; k++) {
            float a = sh2[n*68 + k];
            u64 aa = pack2(a, a);
            float4 w0 = *(const float4*)&sW[(64 + k)*64 + f0];
            float4 w1 = *(const float4*)&sW[(64 + k)*64 + f0 + 4];
            acch[0] = fma2(aa, pack2(w0.x,w0.y), acch[0]);
            acch[1] = fma2(aa, pack2(w0.z,w0.w), acch[1]);
            acch[2] = fma2(aa, pack2(w1.x,w1.y), acch[2]);
            acch[3] = fma2(aa, pack2(w1.z,w1.w), acch[3]);
        }
        float hv[8];
        unpack2(acch[0], hv[0], hv[1]); unpack2(acch[1], hv[2], hv[3]);
        unpack2(acch[2], hv[4], hv[5]); unpack2(acch[3], hv[6], hv[7]);
        float np[8];
#pragma unroll
        for (int u = 0; u < 8; u++) {
            float pvv = sa[n*132 + 64 + f0 + u];
            float h = tanhf(hv[u]);
            np[u] = fmaf(zq[u], h - pvv, pvv);
            sp[n*68 + f0 + u] = np[u];
        }
        float4 o0 = make_float4(np[0],np[1],np[2],np[3]);
        float4 o1 = make_float4(np[4],np[5],np[6],np[7]);
        *(float4*)&g_prop[(size_t)(r0 + n)*Dd + f0]     = o0;
        *(float4*)&g_prop[(size_t)(r0 + n)*Dd + f0 + 4] = o1;
        __syncthreads();   // everyone done with Wh region
        // stage We experts 0..1 -> sW[0:8192]; Wa -> sWa
        for (int i = t; i < 2048; i += 128) cpa16(sWaddr + i*16, We + 4*i);
        for (int i = t; i < 160; i += 128) cpa16(sWaaddr + i*16, Wa + 4*i);
        CP_COMMIT; CP_WAIT0;
        __syncthreads();
    } else {
        // first iteration: prop = inputs; stage all of We + Wa
        for (int i = t; i < 5120; i += 128) cpa16(sWaddr + i*16, We + 4*i);
        for (int i = t; i < 160; i += 128) cpa16(sWaaddr + i*16, Wa + 4*i);
        CP_COMMIT;
        const float4* pr = (const float4*)&inputs[(size_t)(r0 + n)*Dd + f0];
        float4 p0 = pr[0], p1 = pr[1];
        *(float4*)&sp[n*68 + f0]     = p0;
        *(float4*)&sp[n*68 + f0 + 4] = p1;
        CP_WAIT0;
        __syncthreads();
    }

    // msg phase: acc[e][f0..f0+7] over d
    u64 acc[5][4];
#pragma unroll
    for (int e = 0; e < 5; e++) {
        float4 b0 = *(const float4*)&be[e*64 + f0];
        float4 b1 = *(const float4*)&be[e*64 + f0 + 4];
        acc[e][0] = pack2(b0.x, b0.y); acc[e][1] = pack2(b0.z, b0.w);
        acc[e][2] = pack2(b1.x, b1.y); acc[e][3] = pack2(b1.z, b1.w);
    }
#pragma unroll 2
    for (int d = 0; d < 64; d++) {
        float pv = sp[n*68 + d];
        u64 pp = pack2(pv, pv);
#pragma unroll
        for (int e = 0; e < 5; e++) {
            float4 w0 = *(const float4*)&sW[e*4096 + d*64 + f0];
            float4 w1 = *(const float4*)&sW[e*4096 + d*64 + f0 + 4];
            acc[e][0] = fma2(pp, pack2(w0.x,w0.y), acc[e][0]);
            acc[e][1] = fma2(pp, pack2(w0.z,w0.w), acc[e][1]);
            acc[e][2] = fma2(pp, pack2(w1.x,w1.y), acc[e][2]);
            acc[e][3] = fma2(pp, pack2(w1.z,w1.w), acc[e][3]);
        }
    }
    const size_t grow = (size_t)(r0 + n);
#pragma unroll
    for (int e = 0; e < 5; e++) {
        float m[8];
        unpack2(acc[e][0], m[0], m[1]); unpack2(acc[e][1], m[2], m[3]);
        unpack2(acc[e][2], m[4], m[5]); unpack2(acc[e][3], m[6], m[7]);
        float4 v0 = make_float4(m[0],m[1],m[2],m[3]);
        float4 v1 = make_float4(m[4],m[5],m[6],m[7]);
        *(float4*)&g_msg[grow*320 + e*64 + f0]     = v0;
        *(float4*)&g_msg[grow*320 + e*64 + f0 + 4] = v1;
        float rowp = 0.f, colp = 0.f;
#pragma unroll
        for (int u = 0; u < 8; u++) {
            rowp = fmaf(m[u], sWa[e*128 + f0 + u], rowp);
            colp = fmaf(m[u], sWa[e*128 + 64 + f0 + u], colp);
        }
        rowp += __shfl_down_sync(0xffffffffu, rowp, 4, 8);
        rowp += __shfl_down_sync(0xffffffffu, rowp, 2, 8);
        rowp += __shfl_down_sync(0xffffffffu, rowp, 1, 8);
        colp += __shfl_down_sync(0xffffffffu, colp, 4, 8);
        colp += __shfl_down_sync(0xffffffffu, colp, 2, 8);
        colp += __shfl_down_sync(0xffffffffu, colp, 1, 8);
        if (fg == 0) {
            g_row[grow*5 + e]   = rowp;
            g_colba[grow*5 + e] = colp + ba[e];
        }
    }
}

// ---------------------------------------------------------------------------
// Kernel B: scores (sigmoid via MUFU, streamed to out) + merged partial GEMM
// grid 256 (b x 8 j-splits of 16), 256 threads. 4i x 8d register tiles, f32x2.
// ---------------------------------------------------------------------------
extern "C" __global__ void __launch_bounds__(256)
kB(int titer, int do_merge, const int* __restrict__ mask, float* __restrict__ out)
{
    extern __shared__ float sm[];
    float* smsg = sm;                  // [16][320]  5120
    float* ssc  = sm + 5120;           // [128][81]  10368 (pad: bank-conflict-free)
    float* srow = ssc + 10368;         // [128][5]
    float* scol = srow + 640;          // [16][5]
    float* shm  = scol + 80;           // [128][16]  mask as float

    const int b   = blockIdx.x >> 3;
    const int js  = blockIdx.x & 7;
    const int j0  = js * JT;
    const int tid = threadIdx.x;

    unsigned sb = cvta_smem(smsg);
    const float* gm = g_msg + (size_t)(b*Nn + j0) * 320;
    for (int i = tid; i < 1280; i += 256) cpa16(sb + i*16, gm + 4*i);
    CP_COMMIT;
    for (int i = tid; i < 640; i += 256) srow[i] = g_row[b*640 + i];
    for (int i = tid; i < 80;  i += 256) scol[i] = g_colba[(b*Nn + j0)*5 + i];
    for (int i = tid; i < 512; i += 256) {
        int irow = i >> 2, seg = i & 3;
        int4 mv = *(const int4*)&mask[(size_t)(b*Nn + irow)*Nn + j0 + seg*4];
        float* dst = &shm[irow*16 + seg*4];
        dst[0] = (float)mv.x; dst[1] = (float)mv.y;
        dst[2] = (float)mv.z; dst[3] = (float)mv.w;
    }
    CP_WAIT0;
    __syncthreads();

    // scores
    float* outB = out + (((size_t)titer*Bb + b)*Nn*Nn + j0) * Ee;
    for (int idx = tid; idx < Nn*JT*Ee; idx += 256) {
        int i = idx / 80;
        int r = idx - i*80;
        int j = r / 5;
        int e = r - j*5;
        float x = srow[i*5 + e] + scol[j*5 + e];
        float s = shm[i*16 + j] / (1.0f + __expf(-x));
        ssc[i*81 + j*5 + e] = s;
        outB[(size_t)i*640 + j*5 + e] = s;
    }
    if (!do_merge) return;
    __syncthreads();

    // merged partial: [128 i][64 d] over k = 16j x 5e
    const int td = tid & 7, ti = tid >> 3;
    const int d0 = td * 8;
    u64 acc[4][4];
#pragma unroll
    for (int q = 0; q < 4; q++)
#pragma unroll
        for (int h = 0; h < 4; h++) acc[q][h] = 0ull;

#pragma unroll 2
    for (int j = 0; j < JT; j++) {
#pragma unroll
        for (int e = 0; e < 5; e++) {
            const float* mrow = smsg + j*320 + e*64 + d0;
            float4 ma = *(const float4*)mrow;
            float4 mb = *(const float4*)(mrow + 4);
            u64 m0 = pack2(ma.x, ma.y), m1 = pack2(ma.z, ma.w);
            u64 m2 = pack2(mb.x, mb.y), m3 = pack2(mb.z, mb.w);
            const float* sc = ssc + ti*4*81 + j*5 + e;
#pragma unroll
            for (int q = 0; q < 4; q++) {
                float s = sc[q*81];
                u64 ss = pack2(s, s);
                acc[q][0] = fma2(ss, m0, acc[q][0]);
                acc[q][1] = fma2(ss, m1, acc[q][1]);
                acc[q][2] = fma2(ss, m2, acc[q][2]);
                acc[q][3] = fma2(ss, m3, acc[q][3]);
            }
        }
    }
#pragma unroll
    for (int q = 0; q < 4; q++) {
        float v[8];
        unpack2(acc[q][0], v[0], v[1]); unpack2(acc[q][1], v[2], v[3]);
        unpack2(acc[q][2], v[4], v[5]); unpack2(acc[q][3], v[6], v[7]);
        float* dst = &g_part[js][b*Nn + ti*4 + q][d0];
        *(float4*)dst       = make_float4(v[0],v[1],v[2],v[3]);
        *(float4*)(dst + 4) = make_float4(v[4],v[5],v[6],v[7]);
    }
}

// ---------------------------------------------------------------------------
extern "C" void kernel_launch(void* const* d_in, const int* in_sizes, int n_in,
                              void* d_out, int out_size) {
    const float* inputs = (const float*)d_in[0];
    const int*   mask   = (const int*)  d_in[1];
    const float* We     = (const float*)d_in[2];
    const float* be     = (const float*)d_in[3];
    const float* Wa     = (const float*)d_in[4];
    const float* ba     = (const float*)d_in[5];
    const float* Wr     = (const float*)d_in[6];
    const float* br     = (const float*)d_in[7];
    const float* Wz     = (const float*)d_in[8];
    const float* bz     = (const float*)d_in[9];
    const float* Wh     = (const float*)d_in[10];
    const float* bh     = (const float*)d_in[11];
    float* out = (float*)d_out;

    const int SMEM_A = (20480 + ROWS*132 + ROWS*68 + ROWS*68 + 640) * 4;  // 101632
    const int SMEM_B = (5120 + 10368 + 640 + 80 + 2048) * 4;              // 73024
    cudaFuncSetAttribute(kA, cudaFuncAttributeMaxDynamicSharedMemorySize, SMEM_A);
    cudaFuncSetAttribute(kB, cudaFuncAttributeMaxDynamicSharedMemorySize, SMEM_B);

    for (int t = 0; t < T_ITERS; t++) {
        kA<<<Bb*Nn/ROWS, 128, SMEM_A>>>(t, inputs, We, be, Wa, ba,
                                        Wr, br, Wz, bz, Wh, bh);
        kB<<<Bb*JSPLIT, 256, SMEM_B>>>(t, (t < T_ITERS - 1) ? 1 : 0, mask, out);
    }
}

// round 5
// speedup vs baseline: 1.4438x; 1.4438x over previous
#include <cuda_runtime.h>

#define Bb 32
#define Nn 128
#define Dd 64
#define Ee 5
#define T_ITERS 6
#define GRID 128
#define THREADS 256
#define ROWS 32     // rows per block (4096 / 128)
#define JS 4
#define JT 32       // Nn / JS

// smem layout (float offsets)
#define OFF_WR   0        // 8192
#define OFF_WZ   8192     // 8192
#define OFF_WH   16384    // 8192
#define OFF_WE   24576    // 20480
#define OFF_WA   45056    // 640
#define OFF_SA   45696    // 32*68 merged
#define OFF_SP   47872    // 32*68 prop (persists across iterations!)
#define OFF_SH2  50048    // 32*68 r*prop
#define SMEM_FLOATS 52224
// phase-2 overlay (all < OFF_SA, so sa/sp/sh2 survive)
#define OFF_MSG  0        // 32*320 (written by msg phase in-place)
#define OFF_SSC  10240    // 128*161
#define OFF_SROW 30848    // 640
#define OFF_SCOL 31488    // 160
#define OFF_MASK 31648    // 128*32

__device__ float g_rowg[Bb*Nn*Ee];
__device__ float g_colba[Bb*Nn*Ee];
__device__ float g_part[JS][Bb*Nn][Dd];
__device__ volatile int g_gen;
__device__ int g_count;

typedef unsigned long long u64;

__device__ __forceinline__ u64 pack2(float a, float b) {
    u64 r; asm("mov.b64 %0, {%1,%2};" : "=l"(r) : "f"(a), "f"(b)); return r;
}
__device__ __forceinline__ void unpack2(u64 v, float& a, float& b) {
    float x, y; asm("mov.b64 {%0,%1}, %2;" : "=f"(x), "=f"(y) : "l"(v));
    a = x; b = y;
}
__device__ __forceinline__ u64 fma2(u64 a, u64 b, u64 c) {
    u64 d; asm("fma.rn.f32x2 %0, %1, %2, %3;" : "=l"(d) : "l"(a), "l"(b), "l"(c)); return d;
}
__device__ __forceinline__ float sig(float x) { return 1.0f / (1.0f + __expf(-x)); }

__device__ __forceinline__ unsigned cvta_smem(const void* p) {
    return (unsigned)__cvta_generic_to_shared(p);
}
__device__ __forceinline__ void cpa16(unsigned dst, const void* src) {
    asm volatile("cp.async.ca.shared.global [%0], [%1], 16;" :: "r"(dst), "l"(src));
}
#define CP_COMMIT  asm volatile("cp.async.commit_group;" ::: "memory")
#define CP_WAIT(n) asm volatile("cp.async.wait_group %0;" :: "n"(n) : "memory")

// grid-wide barrier: all GRID blocks are co-resident (1 block/SM, GRID < #SMs)
__device__ __forceinline__ void grid_bar() {
    __syncthreads();
    if (threadIdx.x == 0) {
        __threadfence();
        int gen = g_gen;
        if (atomicAdd(&g_count, 1) == GRID - 1) {
            g_count = 0;
            __threadfence();
            g_gen = gen + 1;
        } else {
            while (g_gen == gen) __nanosleep(64);
        }
    }
    __syncthreads();
}

extern "C" __global__ void __launch_bounds__(THREADS)
grrn(const float* __restrict__ inputs, const int* __restrict__ mask,
     const float* __restrict__ We, const float* __restrict__ be,
     const float* __restrict__ Wa, const float* __restrict__ ba,
     const float* __restrict__ Wr, const float* __restrict__ br,
     const float* __restrict__ Wz, const float* __restrict__ bz,
     const float* __restrict__ Wh, const float* __restrict__ bh,
     float* __restrict__ out)
{
    extern __shared__ float sm[];
    const int tid = threadIdx.x;
    const int blk = blockIdx.x;
    const int r0  = blk * ROWS;
    const int b   = blk >> 2;
    const int js  = blk & 3;
    const int j0  = js * JT;
    // phase-1 thread map: 16 f-groups (4-wide) x 16 n-groups (2 rows each)
    const int fg = tid & 15;
    const int f0 = fg * 4;
    const int ng = tid >> 4;
    const int n0 = 2*ng, n1 = 2*ng + 1;
    const unsigned sb = cvta_smem(sm);

    for (int t = 0; t < T_ITERS; t++) {
        // ================= PHASE 1: GRU + msg =================
        // stage group 1: Wr, Wz
        for (int i = tid; i < 2048; i += THREADS) {
            cpa16(sb + (OFF_WR)*4 + i*16, Wr + 4*i);
            cpa16(sb + (OFF_WZ)*4 + i*16, Wz + 4*i);
        }
        CP_COMMIT;
        // stage group 2: Wh, We, Wa
        for (int i = tid; i < 2048; i += THREADS)
            cpa16(sb + (OFF_WH)*4 + i*16, Wh + 4*i);
        for (int i = tid; i < 5120; i += THREADS)
            cpa16(sb + (OFF_WE)*4 + i*16, We + 4*i);
        for (int i = tid; i < 160; i += THREADS)
            cpa16(sb + (OFF_WA)*4 + i*16, Wa + 4*i);
        CP_COMMIT;

        if (t == 0) {
            float4 p0 = *(const float4*)&inputs[(size_t)(r0+n0)*Dd + f0];
            float4 p1 = *(const float4*)&inputs[(size_t)(r0+n1)*Dd + f0];
            *(float4*)&sm[OFF_SP + n0*68 + f0] = p0;
            *(float4*)&sm[OFF_SP + n1*68 + f0] = p1;
            CP_WAIT(0);
            __syncthreads();
        } else {
            // merged = sum of 4 partials (cross-block -> .cg); pold from own smem
            float4 pold0 = *(const float4*)&sm[OFF_SP + n0*68 + f0];
            float4 pold1 = *(const float4*)&sm[OFF_SP + n1*68 + f0];
            float4 m0 = make_float4(0.f,0.f,0.f,0.f), m1 = m0;
#pragma unroll
            for (int p = 0; p < JS; p++) {
                float4 a = __ldcg((const float4*)&g_part[p][r0+n0][f0]);
                float4 c = __ldcg((const float4*)&g_part[p][r0+n1][f0]);
                m0.x += a.x; m0.y += a.y; m0.z += a.z; m0.w += a.w;
                m1.x += c.x; m1.y += c.y; m1.z += c.z; m1.w += c.w;
            }
            *(float4*)&sm[OFF_SA + n0*68 + f0] = m0;
            *(float4*)&sm[OFF_SA + n1*68 + f0] = m1;
            CP_WAIT(1);        // Wr, Wz ready
            __syncthreads();

            // ---- r,z gates ----
            float4 brv = __ldg((const float4*)&br[f0]);
            float4 bzv = __ldg((const float4*)&bz[f0]);
            u64 ar0[2] = {pack2(brv.x,brv.y), pack2(brv.z,brv.w)};
            u64 ar1[2] = {ar0[0], ar0[1]};
            u64 az0[2] = {pack2(bzv.x,bzv.y), pack2(bzv.z,bzv.w)};
            u64 az1[2] = {az0[0], az0[1]};
#pragma unroll 4
            for (int k = 0; k < 64; k++) {        // merged part
                float a0 = sm[OFF_SA + n0*68 + k], a1 = sm[OFF_SA + n1*68 + k];
                u64 aa0 = pack2(a0,a0), aa1 = pack2(a1,a1);
                float4 wr = *(const float4*)&sm[OFF_WR + k*64 + f0];
                float4 wz = *(const float4*)&sm[OFF_WZ + k*64 + f0];
                u64 wr01 = pack2(wr.x,wr.y), wr23 = pack2(wr.z,wr.w);
                u64 wz01 = pack2(wz.x,wz.y), wz23 = pack2(wz.z,wz.w);
                ar0[0]=fma2(aa0,wr01,ar0[0]); ar0[1]=fma2(aa0,wr23,ar0[1]);
                ar1[0]=fma2(aa1,wr01,ar1[0]); ar1[1]=fma2(aa1,wr23,ar1[1]);
                az0[0]=fma2(aa0,wz01,az0[0]); az0[1]=fma2(aa0,wz23,az0[1]);
                az1[0]=fma2(aa1,wz01,az1[0]); az1[1]=fma2(aa1,wz23,az1[1]);
            }
#pragma unroll 4
            for (int k = 0; k < 64; k++) {        // prop part
                float a0 = sm[OFF_SP + n0*68 + k], a1 = sm[OFF_SP + n1*68 + k];
                u64 aa0 = pack2(a0,a0), aa1 = pack2(a1,a1);
                float4 wr = *(const float4*)&sm[OFF_WR + (64+k)*64 + f0];
                float4 wz = *(const float4*)&sm[OFF_WZ + (64+k)*64 + f0];
                u64 wr01 = pack2(wr.x,wr.y), wr23 = pack2(wr.z,wr.w);
                u64 wz01 = pack2(wz.x,wz.y), wz23 = pack2(wz.z,wz.w);
                ar0[0]=fma2(aa0,wr01,ar0[0]); ar0[1]=fma2(aa0,wr23,ar0[1]);
                ar1[0]=fma2(aa1,wr01,ar1[0]); ar1[1]=fma2(aa1,wr23,ar1[1]);
                az0[0]=fma2(aa0,wz01,az0[0]); az0[1]=fma2(aa0,wz23,az0[1]);
                az1[0]=fma2(aa1,wz01,az1[0]); az1[1]=fma2(aa1,wz23,az1[1]);
            }
            float rv0[4], rv1[4], zq0[4], zq1[4];
            unpack2(ar0[0],rv0[0],rv0[1]); unpack2(ar0[1],rv0[2],rv0[3]);
            unpack2(ar1[0],rv1[0],rv1[1]); unpack2(ar1[1],rv1[2],rv1[3]);
            { float z0,z1,z2,z3;
              unpack2(az0[0],z0,z1); unpack2(az0[1],z2,z3);
              zq0[0]=sig(z0); zq0[1]=sig(z1); zq0[2]=sig(z2); zq0[3]=sig(z3);
              unpack2(az1[0],z0,z1); unpack2(az1[1],z2,z3);
              zq1[0]=sig(z0); zq1[1]=sig(z1); zq1[2]=sig(z2); zq1[3]=sig(z3); }
            const float* pp0 = (const float*)&pold0;
            const float* pp1 = (const float*)&pold1;
#pragma unroll
            for (int u = 0; u < 4; u++) {
                sm[OFF_SH2 + n0*68 + f0 + u] = sig(rv0[u]) * pp0[u];
                sm[OFF_SH2 + n1*68 + f0 + u] = sig(rv1[u]) * pp1[u];
            }
            CP_WAIT(0);        // Wh, We, Wa ready
            __syncthreads();   // sh2 visible

            // ---- h gate ----
            float4 bhv = __ldg((const float4*)&bh[f0]);
            u64 ah0[2] = {pack2(bhv.x,bhv.y), pack2(bhv.z,bhv.w)};
            u64 ah1[2] = {ah0[0], ah0[1]};
#pragma unroll 4
            for (int k = 0; k < 64; k++) {        // merged part
                float a0 = sm[OFF_SA + n0*68 + k], a1 = sm[OFF_SA + n1*68 + k];
                u64 aa0 = pack2(a0,a0), aa1 = pack2(a1,a1);
                float4 w = *(const float4*)&sm[OFF_WH + k*64 + f0];
                u64 w01 = pack2(w.x,w.y), w23 = pack2(w.z,w.w);
                ah0[0]=fma2(aa0,w01,ah0[0]); ah0[1]=fma2(aa0,w23,ah0[1]);
                ah1[0]=fma2(aa1,w01,ah1[0]); ah1[1]=fma2(aa1,w23,ah1[1]);
            }
#pragma unroll 4
            for (int k = 0; k < 64; k++) {        // r*prop part
                float a0 = sm[OFF_SH2 + n0*68 + k], a1 = sm[OFF_SH2 + n1*68 + k];
                u64 aa0 = pack2(a0,a0), aa1 = pack2(a1,a1);
                float4 w = *(const float4*)&sm[OFF_WH + (64+k)*64 + f0];
                u64 w01 = pack2(w.x,w.y), w23 = pack2(w.z,w.w);
                ah0[0]=fma2(aa0,w01,ah0[0]); ah0[1]=fma2(aa0,w23,ah0[1]);
                ah1[0]=fma2(aa1,w01,ah1[0]); ah1[1]=fma2(aa1,w23,ah1[1]);
            }
            float hv0[4], hv1[4], np0[4], np1[4];
            unpack2(ah0[0],hv0[0],hv0[1]); unpack2(ah0[1],hv0[2],hv0[3]);
            unpack2(ah1[0],hv1[0],hv1[1]); unpack2(ah1[1],hv1[2],hv1[3]);
#pragma unroll
            for (int u = 0; u < 4; u++) {
                np0[u] = fmaf(zq0[u], tanhf(hv0[u]) - pp0[u], pp0[u]);
                np1[u] = fmaf(zq1[u], tanhf(hv1[u]) - pp1[u], pp1[u]);
            }
            *(float4*)&sm[OFF_SP + n0*68 + f0] = make_float4(np0[0],np0[1],np0[2],np0[3]);
            *(float4*)&sm[OFF_SP + n1*68 + f0] = make_float4(np1[0],np1[1],np1[2],np1[3]);
            __syncthreads();   // sp visible for msg
        }

        // ---- msg GEMM: smsg[n][e*64+f] = prop @ We + be ; row/col ----
        u64 acc[5][2][2];
#pragma unroll
        for (int e = 0; e < 5; e++) {
            float4 bev = __ldg((const float4*)&be[e*64 + f0]);
            acc[e][0][0] = pack2(bev.x,bev.y); acc[e][0][1] = pack2(bev.z,bev.w);
            acc[e][1][0] = acc[e][0][0];       acc[e][1][1] = acc[e][0][1];
        }
#pragma unroll 2
        for (int d = 0; d < 64; d++) {
            float p0 = sm[OFF_SP + n0*68 + d];
            float p1 = sm[OFF_SP + n1*68 + d];
            u64 pp0 = pack2(p0,p0), pp1 = pack2(p1,p1);
#pragma unroll
            for (int e = 0; e < 5; e++) {
                float4 w = *(const float4*)&sm[OFF_WE + e*4096 + d*64 + f0];
                u64 w01 = pack2(w.x,w.y), w23 = pack2(w.z,w.w);
                acc[e][0][0] = fma2(pp0, w01, acc[e][0][0]);
                acc[e][0][1] = fma2(pp0, w23, acc[e][0][1]);
                acc[e][1][0] = fma2(pp1, w01, acc[e][1][0]);
                acc[e][1][1] = fma2(pp1, w23, acc[e][1][1]);
            }
        }
        __syncthreads();   // rz/h consumers of sWr region are done; safe to overlay smsg
#pragma unroll
        for (int e = 0; e < 5; e++) {
#pragma unroll
            for (int rr = 0; rr < 2; rr++) {
                int n = (rr == 0) ? n0 : n1;
                float m[4];
                unpack2(acc[e][rr][0], m[0], m[1]);
                unpack2(acc[e][rr][1], m[2], m[3]);
                *(float4*)&sm[OFF_MSG + n*320 + e*64 + f0] = make_float4(m[0],m[1],m[2],m[3]);
                float rowp = 0.f, colp = 0.f;
#pragma unroll
                for (int u = 0; u < 4; u++) {
                    rowp = fmaf(m[u], sm[OFF_WA + e*128 + f0 + u], rowp);
                    colp = fmaf(m[u], sm[OFF_WA + e*128 + 64 + f0 + u], colp);
                }
#pragma unroll
                for (int o = 8; o > 0; o >>= 1) {
                    rowp += __shfl_down_sync(0xffffffffu, rowp, o, 16);
                    colp += __shfl_down_sync(0xffffffffu, colp, o, 16);
                }
                if (fg == 0) {
                    int grow = r0 + n;
                    g_rowg[grow*5 + e]  = rowp;
                    g_colba[grow*5 + e] = colp + __ldg(&ba[e]);
                }
            }
        }
        grid_bar();

        // ================= PHASE 2: scores + merged =================
        for (int i = tid; i < 640; i += THREADS)
            sm[OFF_SROW + i] = __ldcg(&g_rowg[b*640 + i]);
        for (int i = tid; i < 160; i += THREADS)
            sm[OFF_SCOL + i] = __ldcg(&g_colba[(b*Nn + j0)*5 + i]);
        for (int i = tid; i < 1024; i += THREADS) {
            int irow = i >> 3, seg = i & 7;
            int4 mv = __ldg((const int4*)&mask[(size_t)(b*Nn + irow)*Nn + j0 + seg*4]);
            float* dst = &sm[OFF_MASK + irow*32 + seg*4];
            dst[0] = (float)mv.x; dst[1] = (float)mv.y;
            dst[2] = (float)mv.z; dst[3] = (float)mv.w;
        }
        __syncthreads();

        float* outB = out + (size_t)(t*Bb + b)*(Nn*Nn*Ee) + (size_t)j0*Ee;
#pragma unroll 4
        for (int p = 0; p < 80; p++) {
            int idx = p*256 + tid;
            int i = idx / 160;
            int r = idx - i*160;      // j*5 + e
            int j = r / 5;
            int e = r - j*5;
            float x = sm[OFF_SROW + i*5 + e] + sm[OFF_SCOL + r];
            float s = sm[OFF_MASK + i*32 + j] / (1.0f + __expf(-x));
            sm[OFF_SSC + i*161 + r] = s;
            outB[(size_t)i*(Nn*Ee) + r] = s;
        }

        if (t < T_ITERS - 1) {
            __syncthreads();
            const int td = tid & 7, ti = tid >> 3;
            const int d0 = td * 8;
            u64 a2[4][4];
#pragma unroll
            for (int q = 0; q < 4; q++)
#pragma unroll
                for (int h = 0; h < 4; h++) a2[q][h] = 0ull;
#pragma unroll 1
            for (int j = 0; j < JT; j++) {
#pragma unroll
                for (int e = 0; e < 5; e++) {
                    const float* mr = &sm[OFF_MSG + j*320 + e*64 + d0];
                    float4 ma = *(const float4*)mr;
                    float4 mb = *(const float4*)(mr + 4);
                    u64 m0 = pack2(ma.x,ma.y), m1 = pack2(ma.z,ma.w);
                    u64 m2 = pack2(mb.x,mb.y), m3 = pack2(mb.z,mb.w);
                    const float* sc = &sm[OFF_SSC + ti*4*161 + j*5 + e];
#pragma unroll
                    for (int q = 0; q < 4; q++) {
                        float s = sc[q*161];
                        u64 ss = pack2(s,s);
                        a2[q][0] = fma2(ss, m0, a2[q][0]);
                        a2[q][1] = fma2(ss, m1, a2[q][1]);
                        a2[q][2] = fma2(ss, m2, a2[q][2]);
                        a2[q][3] = fma2(ss, m3, a2[q][3]);
                    }
                }
            }
#pragma unroll
            for (int q = 0; q < 4; q++) {
                float v[8];
                unpack2(a2[q][0], v[0], v[1]); unpack2(a2[q][1], v[2], v[3]);
                unpack2(a2[q][2], v[4], v[5]); unpack2(a2[q][3], v[6], v[7]);
                float* dst = &g_part[js][b*Nn + ti*4 + q][d0];
                *(float4*)dst       = make_float4(v[0],v[1],v[2],v[3]);
                *(float4*)(dst + 4) = make_float4(v[4],v[5],v[6],v[7]);
            }
            grid_bar();
        }
    }
}

extern "C" void kernel_launch(void* const* d_in, const int* in_sizes, int n_in,
                              void* d_out, int out_size) {
    const float* inputs = (const float*)d_in[0];
    const int*   mask   = (const int*)  d_in[1];
    const float* We     = (const float*)d_in[2];
    const float* be     = (const float*)d_in[3];
    const float* Wa     = (const float*)d_in[4];
    const float* ba     = (const float*)d_in[5];
    const float* Wr     = (const float*)d_in[6];
    const float* br     = (const float*)d_in[7];
    const float* Wz     = (const float*)d_in[8];
    const float* bz     = (const float*)d_in[9];
    const float* Wh     = (const float*)d_in[10];
    const float* bh     = (const float*)d_in[11];
    float* out = (float*)d_out;

    static int configured = 0;
    if (!configured) {
        cudaFuncSetAttribute(grrn, cudaFuncAttributeMaxDynamicSharedMemorySize,
                             SMEM_FLOATS * 4);
        configured = 1;
    }
    grrn<<<GRID, THREADS, SMEM_FLOATS * 4>>>(inputs, mask, We, be, Wa, ba,
                                             Wr, br, Wz, bz, Wh, bh, out);
}

// round 6
// speedup vs baseline: 1.6671x; 1.1547x over previous
#include <cuda_runtime.h>

#define Bb 32
#define Nn 128
#define Dd 64
#define Ee 5
#define T_ITERS 6
#define GRID 128
#define THREADS 512
#define ROWS 32     // rows per block
#define JS 4
#define JT 32       // Nn / JS

// ---- smem layout (float offsets) ----
#define OFF_WR   0        // 8192
#define OFF_WZ   8192     // 8192
#define OFF_WH   16384    // 8192
#define OFF_WE   24576    // 20480
#define OFF_WA   45056    // 640
#define OFF_SA   45696    // 32*68 merged
#define OFF_SP   47872    // 32*68 prop (persists across iterations)
#define OFF_SH2  50048    // 32*68 r*prop
#define OFF_SCR  52224    // 4096 reduction scratch
#define SMEM_FLOATS 56320
// phase-2 overlay (never touches OFF_SA..OFF_SCR region except SA which is dead)
#define OFF_MSG  0        // 32*320
#define OFF_SSC  10240    // 128*161
#define OFF_SROW 30848    // 640
#define OFF_SCOL 31488    // 160
#define OFF_MASK 31648    // 128*32

__device__ float g_rowg[Bb*Nn*Ee];
__device__ float g_colba[Bb*Nn*Ee];
__device__ float g_part[JS][Bb*Nn][Dd];
__device__ volatile int g_gen;
__device__ int g_count;

typedef unsigned long long u64;

__device__ __forceinline__ u64 pack2(float a, float b) {
    u64 r; asm("mov.b64 %0, {%1,%2};" : "=l"(r) : "f"(a), "f"(b)); return r;
}
__device__ __forceinline__ void unpack2(u64 v, float& a, float& b) {
    float x, y; asm("mov.b64 {%0,%1}, %2;" : "=f"(x), "=f"(y) : "l"(v));
    a = x; b = y;
}
__device__ __forceinline__ u64 fma2(u64 a, u64 b, u64 c) {
    u64 d; asm("fma.rn.f32x2 %0, %1, %2, %3;" : "=l"(d) : "l"(a), "l"(b), "l"(c)); return d;
}
__device__ __forceinline__ float sigf(float x) {
    return __fdividef(1.0f, 1.0f + __expf(-x));
}
__device__ __forceinline__ float tanhff(float x) {
    return fmaf(2.0f, sigf(2.0f * x), -1.0f);
}
__device__ __forceinline__ unsigned cvta_smem(const void* p) {
    return (unsigned)__cvta_generic_to_shared(p);
}
__device__ __forceinline__ void cpa16(unsigned dst, const void* src) {
    asm volatile("cp.async.ca.shared.global [%0], [%1], 16;" :: "r"(dst), "l"(src));
}
#define CP_COMMIT  asm volatile("cp.async.commit_group;" ::: "memory")
#define CP_WAIT(n) asm volatile("cp.async.wait_group %0;" :: "n"(n) : "memory")

// grid-wide barrier: all GRID blocks co-resident (1 block/SM, GRID < #SMs)
__device__ __forceinline__ void grid_bar() {
    __threadfence();
    __syncthreads();
    if (threadIdx.x == 0) {
        int gen = g_gen;
        if (atomicAdd(&g_count, 1) == GRID - 1) {
            g_count = 0;
            __threadfence();
            g_gen = gen + 1;
        } else {
            while (g_gen == gen) __nanosleep(64);
        }
    }
    __syncthreads();
}

// msg partial for NE experts starting at EBEG (expert-split across thread halves)
template<int NE, int EBEG>
__device__ __forceinline__ void msg_part(
    float* sm, const float* __restrict__ be, const float* __restrict__ ba,
    int n0, int n1, int f0, int fg, int r0)
{
    u64 macc[NE][2][2];
#pragma unroll
    for (int ee = 0; ee < NE; ee++) {
        float4 bev = __ldg((const float4*)&be[(EBEG + ee)*64 + f0]);
        macc[ee][0][0] = pack2(bev.x, bev.y);
        macc[ee][0][1] = pack2(bev.z, bev.w);
        macc[ee][1][0] = macc[ee][0][0];
        macc[ee][1][1] = macc[ee][0][1];
    }
#pragma unroll 2
    for (int d = 0; d < 64; d++) {
        float p0 = sm[OFF_SP + n0*68 + d];
        float p1 = sm[OFF_SP + n1*68 + d];
        u64 pp0 = pack2(p0, p0), pp1 = pack2(p1, p1);
#pragma unroll
        for (int ee = 0; ee < NE; ee++) {
            float4 w = *(const float4*)&sm[OFF_WE + (EBEG + ee)*4096 + d*64 + f0];
            u64 w01 = pack2(w.x, w.y), w23 = pack2(w.z, w.w);
            macc[ee][0][0] = fma2(pp0, w01, macc[ee][0][0]);
            macc[ee][0][1] = fma2(pp0, w23, macc[ee][0][1]);
            macc[ee][1][0] = fma2(pp1, w01, macc[ee][1][0]);
            macc[ee][1][1] = fma2(pp1, w23, macc[ee][1][1]);
        }
    }
    __syncthreads();   // all WE reads done before MSG overlay writes
#pragma unroll
    for (int ee = 0; ee < NE; ee++) {
        int e = EBEG + ee;
#pragma unroll
        for (int rr = 0; rr < 2; rr++) {
            int n = (rr == 0) ? n0 : n1;
            float m[4];
            unpack2(macc[ee][rr][0], m[0], m[1]);
            unpack2(macc[ee][rr][1], m[2], m[3]);
            *(float4*)&sm[OFF_MSG + n*320 + e*64 + f0] = make_float4(m[0],m[1],m[2],m[3]);
            float rowp = 0.f, colp = 0.f;
#pragma unroll
            for (int u = 0; u < 4; u++) {
                rowp = fmaf(m[u], sm[OFF_WA + e*128 + f0 + u], rowp);
                colp = fmaf(m[u], sm[OFF_WA + e*128 + 64 + f0 + u], colp);
            }
#pragma unroll
            for (int o = 8; o > 0; o >>= 1) {
                rowp += __shfl_down_sync(0xffffffffu, rowp, o, 16);
                colp += __shfl_down_sync(0xffffffffu, colp, o, 16);
            }
            if (fg == 0) {
                int grow = r0 + n;
                g_rowg[grow*5 + e]  = rowp;
                g_colba[grow*5 + e] = colp + __ldg(&ba[e]);
            }
        }
    }
}

extern "C" __global__ void __launch_bounds__(THREADS)
grrn(const float* __restrict__ inputs, const int* __restrict__ mask,
     const float* __restrict__ We, const float* __restrict__ be,
     const float* __restrict__ Wa, const float* __restrict__ ba,
     const float* __restrict__ Wr, const float* __restrict__ br,
     const float* __restrict__ Wz, const float* __restrict__ bz,
     const float* __restrict__ Wh, const float* __restrict__ bh,
     float* __restrict__ out)
{
    extern __shared__ float sm[];
    const int tid = threadIdx.x;
    const int blk = blockIdx.x;
    const int r0  = blk * ROWS;
    const int b   = blk >> 2;
    const int js  = blk & 3;
    const int j0  = js * JT;
    // phase-1 map: fg(16, 4-wide) x ng(16, 2 rows) x ks(2, k/e split)
    const int fg = tid & 15;
    const int f0 = fg * 4;
    const int ng = (tid >> 4) & 15;
    const int ks = tid >> 8;            // 0 or 1
    const int n0 = 2*ng, n1 = n0 + 1;
    const unsigned sb = cvta_smem(sm);

    for (int t = 0; t < T_ITERS; t++) {
        // ---- stage weights ----
        for (int i = tid; i < 2048; i += THREADS) {
            cpa16(sb + OFF_WR*4 + i*16, Wr + 4*i);
            cpa16(sb + OFF_WZ*4 + i*16, Wz + 4*i);
        }
        CP_COMMIT;
        for (int i = tid; i < 2048; i += THREADS)
            cpa16(sb + OFF_WH*4 + i*16, Wh + 4*i);
        for (int i = tid; i < 5120; i += THREADS)
            cpa16(sb + OFF_WE*4 + i*16, We + 4*i);
        if (tid < 160) cpa16(sb + OFF_WA*4 + tid*16, Wa + 4*tid);
        CP_COMMIT;

        if (t == 0) {
            int rr = tid >> 4;   // 0..31
            float4 p = *(const float4*)&inputs[(size_t)(r0 + rr)*Dd + f0];
            *(float4*)&sm[OFF_SP + rr*68 + f0] = p;
            CP_WAIT(0);
            __syncthreads();
        } else {
            // merged = sum of 4 partials; one float4 per thread
            {
                int rr = tid >> 4;
                float4 m = make_float4(0.f,0.f,0.f,0.f);
#pragma unroll
                for (int p = 0; p < JS; p++) {
                    float4 a = __ldcg((const float4*)&g_part[p][r0 + rr][f0]);
                    m.x += a.x; m.y += a.y; m.z += a.z; m.w += a.w;
                }
                *(float4*)&sm[OFF_SA + rr*68 + f0] = m;
            }
            CP_WAIT(1);        // Wr, Wz ready
            __syncthreads();

            // ---- rz gates, k-split: ks0 merged@W[0:64], ks1 prop@W[64:128] ----
            const int abase = ks ? OFF_SP : OFF_SA;
            const int kr = ks * 64;
            u64 ar0[2], ar1[2], az0[2], az1[2];
            if (ks == 0) {
                float4 brv = __ldg((const float4*)&br[f0]);
                float4 bzv = __ldg((const float4*)&bz[f0]);
                ar0[0] = pack2(brv.x,brv.y); ar0[1] = pack2(brv.z,brv.w);
                az0[0] = pack2(bzv.x,bzv.y); az0[1] = pack2(bzv.z,bzv.w);
            } else {
                ar0[0] = ar0[1] = az0[0] = az0[1] = 0ull;
            }
            ar1[0] = ar0[0]; ar1[1] = ar0[1];
            az1[0] = az0[0]; az1[1] = az0[1];
#pragma unroll 4
            for (int k = 0; k < 64; k++) {
                float a0 = sm[abase + n0*68 + k], a1 = sm[abase + n1*68 + k];
                u64 aa0 = pack2(a0,a0), aa1 = pack2(a1,a1);
                float4 wr = *(const float4*)&sm[OFF_WR + (kr + k)*64 + f0];
                float4 wz = *(const float4*)&sm[OFF_WZ + (kr + k)*64 + f0];
                u64 wr01 = pack2(wr.x,wr.y), wr23 = pack2(wr.z,wr.w);
                u64 wz01 = pack2(wz.x,wz.y), wz23 = pack2(wz.z,wz.w);
                ar0[0]=fma2(aa0,wr01,ar0[0]); ar0[1]=fma2(aa0,wr23,ar0[1]);
                ar1[0]=fma2(aa1,wr01,ar1[0]); ar1[1]=fma2(aa1,wr23,ar1[1]);
                az0[0]=fma2(aa0,wz01,az0[0]); az0[1]=fma2(aa0,wz23,az0[1]);
                az1[0]=fma2(aa1,wz01,az1[0]); az1[1]=fma2(aa1,wz23,az1[1]);
            }
            if (ks == 1) {
                u64* s = (u64*)&sm[OFF_SCR + (tid - 256)*16];
                s[0]=ar0[0]; s[1]=ar0[1]; s[2]=ar1[0]; s[3]=ar1[1];
                s[4]=az0[0]; s[5]=az0[1]; s[6]=az1[0]; s[7]=az1[1];
            }
            __syncthreads();

            float zq0[4], zq1[4];
            if (ks == 0) {
                const float* s = &sm[OFF_SCR + tid*16];
                float v0[4], v1[4], w0[4], w1[4];
                unpack2(ar0[0], v0[0], v0[1]); unpack2(ar0[1], v0[2], v0[3]);
                unpack2(ar1[0], v1[0], v1[1]); unpack2(ar1[1], v1[2], v1[3]);
                unpack2(az0[0], w0[0], w0[1]); unpack2(az0[1], w0[2], w0[3]);
                unpack2(az1[0], w1[0], w1[1]); unpack2(az1[1], w1[2], w1[3]);
#pragma unroll
                for (int u = 0; u < 4; u++) {
                    float rg0 = sigf(v0[u] + s[u]);
                    float rg1 = sigf(v1[u] + s[4+u]);
                    zq0[u] = sigf(w0[u] + s[8+u]);
                    zq1[u] = sigf(w1[u] + s[12+u]);
                    sm[OFF_SH2 + n0*68 + f0 + u] = rg0 * sm[OFF_SP + n0*68 + f0 + u];
                    sm[OFF_SH2 + n1*68 + f0 + u] = rg1 * sm[OFF_SP + n1*68 + f0 + u];
                }
            }
            CP_WAIT(0);        // Wh, We, Wa ready
            __syncthreads();   // sh2 visible

            // ---- h gate, k-split: ks0 merged@Wh[0:64], ks1 sh2@Wh[64:128] ----
            const int hbase = ks ? OFF_SH2 : OFF_SA;
            u64 ah0[2], ah1[2];
            if (ks == 0) {
                float4 bhv = __ldg((const float4*)&bh[f0]);
                ah0[0] = pack2(bhv.x,bhv.y); ah0[1] = pack2(bhv.z,bhv.w);
            } else {
                ah0[0] = ah0[1] = 0ull;
            }
            ah1[0] = ah0[0]; ah1[1] = ah0[1];
#pragma unroll 4
            for (int k = 0; k < 64; k++) {
                float a0 = sm[hbase + n0*68 + k], a1 = sm[hbase + n1*68 + k];
                u64 aa0 = pack2(a0,a0), aa1 = pack2(a1,a1);
                float4 w = *(const float4*)&sm[OFF_WH + (kr + k)*64 + f0];
                u64 w01 = pack2(w.x,w.y), w23 = pack2(w.z,w.w);
                ah0[0]=fma2(aa0,w01,ah0[0]); ah0[1]=fma2(aa0,w23,ah0[1]);
                ah1[0]=fma2(aa1,w01,ah1[0]); ah1[1]=fma2(aa1,w23,ah1[1]);
            }
            if (ks == 1) {
                u64* s = (u64*)&sm[OFF_SCR + (tid - 256)*8];
                s[0]=ah0[0]; s[1]=ah0[1]; s[2]=ah1[0]; s[3]=ah1[1];
            }
            __syncthreads();
            if (ks == 0) {
                const float* s = &sm[OFF_SCR + tid*8];
                float h0[4], h1[4];
                unpack2(ah0[0], h0[0], h0[1]); unpack2(ah0[1], h0[2], h0[3]);
                unpack2(ah1[0], h1[0], h1[1]); unpack2(ah1[1], h1[2], h1[3]);
                float np0[4], np1[4];
#pragma unroll
                for (int u = 0; u < 4; u++) {
                    float p0v = sm[OFF_SP + n0*68 + f0 + u];
                    float p1v = sm[OFF_SP + n1*68 + f0 + u];
                    np0[u] = fmaf(zq0[u], tanhff(h0[u] + s[u])   - p0v, p0v);
                    np1[u] = fmaf(zq1[u], tanhff(h1[u] + s[4+u]) - p1v, p1v);
                }
                *(float4*)&sm[OFF_SP + n0*68 + f0] = make_float4(np0[0],np0[1],np0[2],np0[3]);
                *(float4*)&sm[OFF_SP + n1*68 + f0] = make_float4(np1[0],np1[1],np1[2],np1[3]);
            }
            __syncthreads();   // new prop visible
        }

        // ---- msg GEMM, expert-split: ks0 -> e{0,1,2}, ks1 -> e{3,4} ----
        if (ks == 0) msg_part<3,0>(sm, be, ba, n0, n1, f0, fg, r0);
        else         msg_part<2,3>(sm, be, ba, n0, n1, f0, fg, r0);
        grid_bar();

        // ================= PHASE 2: scores + merged =================
        for (int i = tid; i < 640; i += THREADS)
            sm[OFF_SROW + i] = __ldcg(&g_rowg[b*640 + i]);
        for (int i = tid; i < 160; i += THREADS)
            sm[OFF_SCOL + i] = __ldcg(&g_colba[(b*Nn + j0)*5 + i]);
        for (int i = tid; i < 1024; i += THREADS) {
            int irow = i >> 3, seg = i & 7;
            int4 mv = __ldg((const int4*)&mask[(size_t)(b*Nn + irow)*Nn + j0 + seg*4]);
            float* dst = &sm[OFF_MASK + irow*32 + seg*4];
            dst[0] = (float)mv.x; dst[1] = (float)mv.y;
            dst[2] = (float)mv.z; dst[3] = (float)mv.w;
        }
        __syncthreads();

        float* outB = out + (size_t)(t*Bb + b)*(Nn*Nn*Ee) + (size_t)j0*Ee;
#pragma unroll 4
        for (int p = 0; p < 40; p++) {
            int idx = p*512 + tid;
            int i = idx / 160;
            int r = idx - i*160;      // j*5 + e
            int j = r / 5;
            float x = sm[OFF_SROW + i*5 + (r - j*5)] + sm[OFF_SCOL + r];
            float s = sm[OFF_MASK + i*32 + j] * __fdividef(1.0f, 1.0f + __expf(-x));
            sm[OFF_SSC + i*161 + r] = s;
            outB[(size_t)i*(Nn*Ee) + r] = s;
        }

        if (t < T_ITERS - 1) {
            __syncthreads();
            const int td = tid & 7, ti = tid >> 3;   // 64 i-groups x 2 rows
            const int d0 = td * 8;
            u64 a2[2][4];
#pragma unroll
            for (int q = 0; q < 2; q++)
#pragma unroll
                for (int h = 0; h < 4; h++) a2[q][h] = 0ull;
#pragma unroll 1
            for (int j = 0; j < JT; j++) {
#pragma unroll
                for (int e = 0; e < 5; e++) {
                    const float* mr = &sm[OFF_MSG + j*320 + e*64 + d0];
                    float4 ma = *(const float4*)mr;
                    float4 mb = *(const float4*)(mr + 4);
                    u64 m0 = pack2(ma.x,ma.y), m1 = pack2(ma.z,ma.w);
                    u64 m2 = pack2(mb.x,mb.y), m3 = pack2(mb.z,mb.w);
                    const float* sc = &sm[OFF_SSC + ti*2*161 + j*5 + e];
#pragma unroll
                    for (int q = 0; q < 2; q++) {
                        float s = sc[q*161];
                        u64 ss = pack2(s,s);
                        a2[q][0] = fma2(ss, m0, a2[q][0]);
                        a2[q][1] = fma2(ss, m1, a2[q][1]);
                        a2[q][2] = fma2(ss, m2, a2[q][2]);
                        a2[q][3] = fma2(ss, m3, a2[q][3]);
                    }
                }
            }
#pragma unroll
            for (int q = 0; q < 2; q++) {
                float v[8];
                unpack2(a2[q][0], v[0], v[1]); unpack2(a2[q][1], v[2], v[3]);
                unpack2(a2[q][2], v[4], v[5]); unpack2(a2[q][3], v[6], v[7]);
                float* dst = &g_part[js][b*Nn + ti*2 + q][d0];
                *(float4*)dst       = make_float4(v[0],v[1],v[2],v[3]);
                *(float4*)(dst + 4) = make_float4(v[4],v[5],v[6],v[7]);
            }
            grid_bar();
        }
    }
}

extern "C" void kernel_launch(void* const* d_in, const int* in_sizes, int n_in,
                              void* d_out, int out_size) {
    const float* inputs = (const float*)d_in[0];
    const int*   mask   = (const int*)  d_in[1];
    const float* We     = (const float*)d_in[2];
    const float* be     = (const float*)d_in[3];
    const float* Wa     = (const float*)d_in[4];
    const float* ba     = (const float*)d_in[5];
    const float* Wr     = (const float*)d_in[6];
    const float* br     = (const float*)d_in[7];
    const float* Wz     = (const float*)d_in[8];
    const float* bz     = (const float*)d_in[9];
    const float* Wh     = (const float*)d_in[10];
    const float* bh     = (const float*)d_in[11];
    float* out = (float*)d_out;

    static int configured = 0;
    if (!configured) {
        cudaFuncSetAttribute(grrn, cudaFuncAttributeMaxDynamicSharedMemorySize,
                             SMEM_FLOATS * 4);
        configured = 1;
    }
    grrn<<<GRID, THREADS, SMEM_FLOATS * 4>>>(inputs, mask, We, be, Wa, ba,
                                             Wr, br, Wz, bz, Wh, bh, out);
}

// round 7
// speedup vs baseline: 1.8233x; 1.0937x over previous
#include <cuda_runtime.h>

#define Bb 32
#define Nn 128
#define Dd 64
#define Ee 5
#define T_ITERS 6
#define GRID 128
#define THREADS 512
#define ROWS 32
#define JS 4
#define JT 32

// ---- smem float offsets (phase 1) ----
#define OFF_WR   0        // 8192
#define OFF_WZ   8192     // 8192
#define OFF_WH   16384    // 8192
#define OFF_WE   24576    // 20480
#define OFF_WA   45056    // 640
#define OFF_SA   45696    // 32*68 merged
#define OFF_SP   47872    // 32*68 prop (persists across iterations)
#define OFF_SH2  50048    // 32*68 r*prop
#define OFF_SCR0 52224    // 128*20
#define OFF_SCR1 54784    // 128*20
#define SMEM_FLOATS 57344
// ---- phase-2 overlay (weights region is dead there; restaged next iter) ----
#define OFF_MSG  0        // 32*320
#define OFF_SSC  10240    // 128*161
#define OFF_SROW 30848    // 640
#define OFF_SCOL 31488    // 160
#define OFF_MASK 31648    // 128*32

__device__ float g_rowg[Bb*Nn*Ee];
__device__ float g_colba[Bb*Nn*Ee];
__device__ float g_part[JS][Bb*Nn][Dd];
__device__ volatile int g_gen;
__device__ int g_count;

typedef unsigned long long u64;

__device__ __forceinline__ u64 pack2(float a, float b) {
    u64 r; asm("mov.b64 %0, {%1,%2};" : "=l"(r) : "f"(a), "f"(b)); return r;
}
__device__ __forceinline__ void unpack2(u64 v, float& a, float& b) {
    float x, y; asm("mov.b64 {%0,%1}, %2;" : "=f"(x), "=f"(y) : "l"(v));
    a = x; b = y;
}
__device__ __forceinline__ u64 fma2(u64 a, u64 b, u64 c) {
    u64 d; asm("fma.rn.f32x2 %0, %1, %2, %3;" : "=l"(d) : "l"(a), "l"(b), "l"(c)); return d;
}
__device__ __forceinline__ u64 add2(u64 a, u64 b) {
    u64 d; asm("add.rn.f32x2 %0, %1, %2;" : "=l"(d) : "l"(a), "l"(b)); return d;
}
__device__ __forceinline__ float sigf(float x) {
    return __fdividef(1.0f, 1.0f + __expf(-x));
}
__device__ __forceinline__ float tanhff(float x) {
    return fmaf(2.0f, sigf(2.0f * x), -1.0f);
}
__device__ __forceinline__ unsigned cvta_smem(const void* p) {
    return (unsigned)__cvta_generic_to_shared(p);
}
__device__ __forceinline__ void cpa16(unsigned dst, const void* src) {
    asm volatile("cp.async.ca.shared.global [%0], [%1], 16;" :: "r"(dst), "l"(src));
}
#define CP_COMMIT  asm volatile("cp.async.commit_group;" ::: "memory")
#define CP_WAIT(n) asm volatile("cp.async.wait_group %0;" :: "n"(n) : "memory")

__device__ __forceinline__ void grid_bar() {
    __threadfence();
    __syncthreads();
    if (threadIdx.x == 0) {
        int gen = g_gen;
        if (atomicAdd(&g_count, 1) == GRID - 1) {
            g_count = 0;
            __threadfence();
            g_gen = gen + 1;
        } else {
            while (g_gen == gen) __nanosleep(64);
        }
    }
    __syncthreads();
}

// scratch: slot stride 20 floats (16 used, 16B-aligned, conflict-spread)
__device__ __forceinline__ void scr_w(float* sm, int base, int slot, const u64 a[4][2]) {
#pragma unroll
    for (int r = 0; r < 4; r++) {
        float x, y, z, w;
        unpack2(a[r][0], x, y); unpack2(a[r][1], z, w);
        *(float4*)&sm[base + slot*20 + r*4] = make_float4(x, y, z, w);
    }
}
__device__ __forceinline__ void scr_a(float* sm, int base, int slot, u64 a[4][2]) {
#pragma unroll
    for (int r = 0; r < 4; r++) {
        float4 v = *(const float4*)&sm[base + slot*20 + r*4];
        a[r][0] = add2(a[r][0], pack2(v.x, v.y));
        a[r][1] = add2(a[r][1], pack2(v.z, v.w));
    }
}

// dual-gate quarter GEMM: 4 rows x 4f over 32 k (shared act loads)
__device__ __forceinline__ void gate_q2(const float* sm, int wb1, int wb2,
                                        int abase, int koff, int kg, int rg, int f0,
                                        u64 ar[4][2], u64 az[4][2]) {
#pragma unroll 2
    for (int s4 = 0; s4 < 32; s4 += 4) {
        float av[4][4];
#pragma unroll
        for (int r = 0; r < 4; r++) {
            float4 tv = *(const float4*)&sm[abase + (rg*4+r)*68 + koff + s4];
            av[r][0]=tv.x; av[r][1]=tv.y; av[r][2]=tv.z; av[r][3]=tv.w;
        }
#pragma unroll
        for (int u = 0; u < 4; u++) {
            int k = kg + s4 + u;
            float4 w1 = *(const float4*)&sm[wb1 + k*64 + f0];
            float4 w2 = *(const float4*)&sm[wb2 + k*64 + f0];
            u64 a01 = pack2(w1.x,w1.y), a23 = pack2(w1.z,w1.w);
            u64 b01 = pack2(w2.x,w2.y), b23 = pack2(w2.z,w2.w);
#pragma unroll
            for (int r = 0; r < 4; r++) {
                u64 aa = pack2(av[r][u], av[r][u]);
                ar[r][0] = fma2(aa, a01, ar[r][0]);
                ar[r][1] = fma2(aa, a23, ar[r][1]);
                az[r][0] = fma2(aa, b01, az[r][0]);
                az[r][1] = fma2(aa, b23, az[r][1]);
            }
        }
    }
}

// single-gate quarter GEMM
__device__ __forceinline__ void gate_q1(const float* sm, int wb,
                                        int abase, int koff, int kg, int rg, int f0,
                                        u64 ah[4][2]) {
#pragma unroll 2
    for (int s4 = 0; s4 < 32; s4 += 4) {
        float av[4][4];
#pragma unroll
        for (int r = 0; r < 4; r++) {
            float4 tv = *(const float4*)&sm[abase + (rg*4+r)*68 + koff + s4];
            av[r][0]=tv.x; av[r][1]=tv.y; av[r][2]=tv.z; av[r][3]=tv.w;
        }
#pragma unroll
        for (int u = 0; u < 4; u++) {
            int k = kg + s4 + u;
            float4 w1 = *(const float4*)&sm[wb + k*64 + f0];
            u64 a01 = pack2(w1.x,w1.y), a23 = pack2(w1.z,w1.w);
#pragma unroll
            for (int r = 0; r < 4; r++) {
                u64 aa = pack2(av[r][u], av[r][u]);
                ah[r][0] = fma2(aa, a01, ah[r][0]);
                ah[r][1] = fma2(aa, a23, ah[r][1]);
            }
        }
    }
}

// msg partial: NE experts x 4 rows x 4f over a 32-d half
template<int NE, int EB>
__device__ __forceinline__ void msg_core(const float* sm, int rg, int f0, int dbase,
                                         u64 m[3][4][2]) {
#pragma unroll 2
    for (int d4 = 0; d4 < 32; d4 += 4) {
        float av[4][4];
#pragma unroll
        for (int r = 0; r < 4; r++) {
            float4 tv = *(const float4*)&sm[OFF_SP + (rg*4+r)*68 + dbase + d4];
            av[r][0]=tv.x; av[r][1]=tv.y; av[r][2]=tv.z; av[r][3]=tv.w;
        }
#pragma unroll
        for (int u = 0; u < 4; u++) {
            int d = dbase + d4 + u;
#pragma unroll
            for (int e = 0; e < NE; e++) {
                float4 w = *(const float4*)&sm[OFF_WE + (EB+e)*4096 + d*64 + f0];
                u64 w01 = pack2(w.x,w.y), w23 = pack2(w.z,w.w);
#pragma unroll
                for (int r = 0; r < 4; r++) {
                    u64 aa = pack2(av[r][u], av[r][u]);
                    m[e][r][0] = fma2(aa, w01, m[e][r][0]);
                    m[e][r][1] = fma2(aa, w23, m[e][r][1]);
                }
            }
        }
    }
}

template<int NE, int EB>
__device__ __forceinline__ void msg_out(float* sm, int rg, int f0, int fg, int r0,
                                        const float* __restrict__ ba, u64 m[3][4][2]) {
#pragma unroll
    for (int e = 0; e < NE; e++) {
        float bav = __ldg(&ba[EB+e]);
#pragma unroll
        for (int r = 0; r < 4; r++) {
            float v0,v1,v2,v3;
            unpack2(m[e][r][0], v0, v1); unpack2(m[e][r][1], v2, v3);
            int row = rg*4 + r;
            *(float4*)&sm[OFF_MSG + row*320 + (EB+e)*64 + f0] = make_float4(v0,v1,v2,v3);
            const float* wa = &sm[OFF_WA + (EB+e)*128 + f0];
            float rowp = v0*wa[0]; rowp = fmaf(v1,wa[1],rowp);
            rowp = fmaf(v2,wa[2],rowp); rowp = fmaf(v3,wa[3],rowp);
            float colp = v0*wa[64]; colp = fmaf(v1,wa[65],colp);
            colp = fmaf(v2,wa[66],colp); colp = fmaf(v3,wa[67],colp);
#pragma unroll
            for (int o = 8; o > 0; o >>= 1) {
                rowp += __shfl_down_sync(0xffffffffu, rowp, o, 16);
                colp += __shfl_down_sync(0xffffffffu, colp, o, 16);
            }
            if (fg == 0) {
                g_rowg[(r0+row)*5 + EB+e]  = rowp;
                g_colba[(r0+row)*5 + EB+e] = colp + bav;
            }
        }
    }
}

extern "C" __global__ void __launch_bounds__(THREADS)
grrn(const float* __restrict__ inputs, const int* __restrict__ mask,
     const float* __restrict__ We, const float* __restrict__ be,
     const float* __restrict__ Wa, const float* __restrict__ ba,
     const float* __restrict__ Wr, const float* __restrict__ br,
     const float* __restrict__ Wz, const float* __restrict__ bz,
     const float* __restrict__ Wh, const float* __restrict__ bh,
     float* __restrict__ out)
{
    extern __shared__ float sm[];
    const int tid  = threadIdx.x;
    const int blk  = blockIdx.x;
    const int r0   = blk * ROWS;
    const int b    = blk >> 2;
    const int js   = blk & 3;
    const int j0   = js * JT;
    const int fg   = tid & 15;
    const int f0   = fg * 4;
    const int rg   = (tid >> 4) & 7;   // 8 row groups x 4 rows
    const int ks   = tid >> 7;         // 0..3 k-quarter / (eg,dg) split
    const int slot = tid & 127;
    const unsigned sb = cvta_smem(sm);

    for (int t = 0; t < T_ITERS; t++) {
        // ---- stage weights: G1=(Wr,Wz) G2=(Wh) G3=(We,Wa) ----
        for (int i = tid; i < 2048; i += THREADS) {
            cpa16(sb + OFF_WR*4 + i*16, Wr + 4*i);
            cpa16(sb + OFF_WZ*4 + i*16, Wz + 4*i);
        }
        CP_COMMIT;
        for (int i = tid; i < 2048; i += THREADS)
            cpa16(sb + OFF_WH*4 + i*16, Wh + 4*i);
        CP_COMMIT;
        for (int i = tid; i < 5120; i += THREADS)
            cpa16(sb + OFF_WE*4 + i*16, We + 4*i);
        if (tid < 160) cpa16(sb + OFF_WA*4 + tid*16, Wa + 4*tid);
        CP_COMMIT;

        if (t == 0) {
            int rr = tid >> 4;   // 0..31
            float4 p = *(const float4*)&inputs[(size_t)(r0 + rr)*Dd + f0];
            *(float4*)&sm[OFF_SP + rr*68 + f0] = p;
            CP_WAIT(0);
            __syncthreads();
        } else {
            // merged = sum of 4 partials
            {
                int rr = tid >> 4;
                float4 msum = make_float4(0.f,0.f,0.f,0.f);
#pragma unroll
                for (int p = 0; p < JS; p++) {
                    float4 a = __ldcg((const float4*)&g_part[p][r0 + rr][f0]);
                    msum.x += a.x; msum.y += a.y; msum.z += a.z; msum.w += a.w;
                }
                *(float4*)&sm[OFF_SA + rr*68 + f0] = msum;
            }
            CP_WAIT(2);          // G1 (Wr,Wz) done
            __syncthreads();

            // ---- rz gates: k-quarter per ks ----
            u64 ar[4][2], az[4][2];
            if (ks == 0) {
                float4 brv = __ldg((const float4*)&br[f0]);
                float4 bzv = __ldg((const float4*)&bz[f0]);
#pragma unroll
                for (int r = 0; r < 4; r++) {
                    ar[r][0] = pack2(brv.x,brv.y); ar[r][1] = pack2(brv.z,brv.w);
                    az[r][0] = pack2(bzv.x,bzv.y); az[r][1] = pack2(bzv.z,bzv.w);
                }
            } else {
#pragma unroll
                for (int r = 0; r < 4; r++)
                    ar[r][0]=ar[r][1]=az[r][0]=az[r][1]=0ull;
            }
            {
                const int abase = (ks < 2) ? OFF_SA : OFF_SP;
                const int koff  = (ks & 1) * 32;
                const int kg    = ks * 32;
                gate_q2(sm, OFF_WR, OFF_WZ, abase, koff, kg, rg, f0, ar, az);
            }
            // reduce r -> ks0, z -> ks1 (3 pipelined rounds)
            if (ks == 2) scr_w(sm, OFF_SCR0, slot, ar);
            if (ks == 3) scr_w(sm, OFF_SCR1, slot, az);
            __syncthreads();
            if (ks == 0) scr_a(sm, OFF_SCR0, slot, ar);
            if (ks == 1) scr_a(sm, OFF_SCR1, slot, az);
            __syncthreads();
            if (ks == 3) scr_w(sm, OFF_SCR0, slot, ar);
            if (ks == 2) scr_w(sm, OFF_SCR1, slot, az);
            __syncthreads();
            if (ks == 0) scr_a(sm, OFF_SCR0, slot, ar);
            if (ks == 1) scr_a(sm, OFF_SCR1, slot, az);
            __syncthreads();
            if (ks == 1) scr_w(sm, OFF_SCR0, slot, ar);
            if (ks == 0) scr_w(sm, OFF_SCR1, slot, az);
            __syncthreads();

            float zq[4][4];
            if (ks == 0) {
                scr_a(sm, OFF_SCR0, slot, ar);   // r complete
#pragma unroll
                for (int r = 0; r < 4; r++) {
                    float x0,x1,x2,x3;
                    unpack2(ar[r][0], x0, x1); unpack2(ar[r][1], x2, x3);
                    int row = rg*4 + r;
                    const float* pp = &sm[OFF_SP + row*68 + f0];
                    float* sh = &sm[OFF_SH2 + row*68 + f0];
                    sh[0] = sigf(x0)*pp[0]; sh[1] = sigf(x1)*pp[1];
                    sh[2] = sigf(x2)*pp[2]; sh[3] = sigf(x3)*pp[3];
                }
            }
            if (ks == 1) {
                scr_a(sm, OFF_SCR1, slot, az);   // z complete
#pragma unroll
                for (int r = 0; r < 4; r++) {
                    float x0,x1,x2,x3;
                    unpack2(az[r][0], x0, x1); unpack2(az[r][1], x2, x3);
                    zq[r][0]=sigf(x0); zq[r][1]=sigf(x1);
                    zq[r][2]=sigf(x2); zq[r][3]=sigf(x3);
                }
            }
            __syncthreads();     // sh2 visible; Wh ready below

            // ---- h gate ----
            CP_WAIT(1);          // G2 (Wh) done
            u64 ah[4][2];
            if (ks == 0) {
                float4 bhv = __ldg((const float4*)&bh[f0]);
#pragma unroll
                for (int r = 0; r < 4; r++) {
                    ah[r][0] = pack2(bhv.x,bhv.y); ah[r][1] = pack2(bhv.z,bhv.w);
                }
            } else {
#pragma unroll
                for (int r = 0; r < 4; r++) ah[r][0]=ah[r][1]=0ull;
            }
            {
                const int hbase = (ks < 2) ? OFF_SA : OFF_SH2;
                const int koff  = (ks & 1) * 32;
                const int kg    = ks * 32;
                gate_q1(sm, OFF_WH, hbase, koff, kg, rg, f0, ah);
            }
            if (ks == 1) scr_w(sm, OFF_SCR0, slot, ah);
            if (ks == 2) scr_w(sm, OFF_SCR1, slot, ah);
            __syncthreads();
            if (ks == 0) { scr_a(sm, OFF_SCR0, slot, ah); scr_a(sm, OFF_SCR1, slot, ah); }
            __syncthreads();
            if (ks == 3) scr_w(sm, OFF_SCR0, slot, ah);
            if (ks == 1) {
#pragma unroll
                for (int r = 0; r < 4; r++)
                    *(float4*)&sm[OFF_SCR1 + slot*20 + r*4] =
                        make_float4(zq[r][0], zq[r][1], zq[r][2], zq[r][3]);
            }
            CP_WAIT(0);          // G3 (We, Wa) done
            __syncthreads();
            if (ks == 0) {
                scr_a(sm, OFF_SCR0, slot, ah);   // h complete
#pragma unroll
                for (int r = 0; r < 4; r++) {
                    float h0,h1,h2,h3;
                    unpack2(ah[r][0], h0, h1); unpack2(ah[r][1], h2, h3);
                    float4 zv = *(const float4*)&sm[OFF_SCR1 + slot*20 + r*4];
                    int row = rg*4 + r;
                    float4 pv = *(const float4*)&sm[OFF_SP + row*68 + f0];
                    float4 np;
                    np.x = fmaf(zv.x, tanhff(h0) - pv.x, pv.x);
                    np.y = fmaf(zv.y, tanhff(h1) - pv.y, pv.y);
                    np.z = fmaf(zv.z, tanhff(h2) - pv.z, pv.z);
                    np.w = fmaf(zv.w, tanhff(h3) - pv.w, pv.w);
                    *(float4*)&sm[OFF_SP + row*68 + f0] = np;
                }
            }
            __syncthreads();     // new prop visible
        }

        // ---- msg GEMM: (eg,dg) split; eg0 -> e{0,1,2}, eg1 -> e{3,4}; dg = d-half ----
        u64 m[3][4][2];
        const int eg = ks >> 1;
        const int dbase = (ks & 1) * 32;
        if (eg == 0) {
            if ((ks & 1) == 0) {
#pragma unroll
                for (int e = 0; e < 3; e++) {
                    float4 bev = __ldg((const float4*)&be[e*64 + f0]);
#pragma unroll
                    for (int r = 0; r < 4; r++) {
                        m[e][r][0] = pack2(bev.x,bev.y); m[e][r][1] = pack2(bev.z,bev.w);
                    }
                }
            } else {
#pragma unroll
                for (int e = 0; e < 3; e++)
#pragma unroll
                    for (int r = 0; r < 4; r++) m[e][r][0]=m[e][r][1]=0ull;
            }
            msg_core<3,0>(sm, rg, f0, dbase, m);
        } else {
            if ((ks & 1) == 0) {
#pragma unroll
                for (int e = 0; e < 2; e++) {
                    float4 bev = __ldg((const float4*)&be[(3+e)*64 + f0]);
#pragma unroll
                    for (int r = 0; r < 4; r++) {
                        m[e][r][0] = pack2(bev.x,bev.y); m[e][r][1] = pack2(bev.z,bev.w);
                    }
                }
            } else {
#pragma unroll
                for (int e = 0; e < 2; e++)
#pragma unroll
                    for (int r = 0; r < 4; r++) m[e][r][0]=m[e][r][1]=0ull;
            }
            msg_core<2,3>(sm, rg, f0, dbase, m);
        }
        // reduce dg1 -> dg0, expert-by-expert
        if (ks == 1) scr_w(sm, OFF_SCR0, slot, m[0]);
        if (ks == 3) scr_w(sm, OFF_SCR1, slot, m[0]);
        __syncthreads();
        if (ks == 0) scr_a(sm, OFF_SCR0, slot, m[0]);
        if (ks == 2) scr_a(sm, OFF_SCR1, slot, m[0]);
        __syncthreads();
        if (ks == 1) scr_w(sm, OFF_SCR0, slot, m[1]);
        if (ks == 3) scr_w(sm, OFF_SCR1, slot, m[1]);
        __syncthreads();
        if (ks == 0) scr_a(sm, OFF_SCR0, slot, m[1]);
        if (ks == 2) scr_a(sm, OFF_SCR1, slot, m[1]);
        __syncthreads();
        if (ks == 1) scr_w(sm, OFF_SCR0, slot, m[2]);
        __syncthreads();
        if (ks == 0) {
            scr_a(sm, OFF_SCR0, slot, m[2]);
            msg_out<3,0>(sm, rg, f0, fg, r0, ba, m);
        }
        if (ks == 2) msg_out<2,3>(sm, rg, f0, fg, r0, ba, m);
        grid_bar();

        // ================= PHASE 2: scores + merged =================
        for (int i = tid; i < 640; i += THREADS)
            sm[OFF_SROW + i] = __ldcg(&g_rowg[b*640 + i]);
        for (int i = tid; i < 160; i += THREADS)
            sm[OFF_SCOL + i] = __ldcg(&g_colba[(b*Nn + j0)*5 + i]);
        for (int i = tid; i < 1024; i += THREADS) {
            int irow = i >> 3, seg = i & 7;
            int4 mv = __ldg((const int4*)&mask[(size_t)(b*Nn + irow)*Nn + j0 + seg*4]);
            float* dst = &sm[OFF_MASK + irow*32 + seg*4];
            dst[0] = (float)mv.x; dst[1] = (float)mv.y;
            dst[2] = (float)mv.z; dst[3] = (float)mv.w;
        }
        __syncthreads();

        float* outB = out + (size_t)(t*Bb + b)*(Nn*Nn*Ee) + (size_t)j0*Ee;
#pragma unroll 4
        for (int p = 0; p < 40; p++) {
            int idx = p*512 + tid;
            int i = idx / 160;
            int r = idx - i*160;
            int j = r / 5;
            float x = sm[OFF_SROW + i*5 + (r - j*5)] + sm[OFF_SCOL + r];
            float s = sm[OFF_MASK + i*32 + j] * __fdividef(1.0f, 1.0f + __expf(-x));
            sm[OFF_SSC + i*161 + r] = s;
            outB[(size_t)i*(Nn*Ee) + r] = s;
        }

        if (t < T_ITERS - 1) {
            __syncthreads();
            const int td = tid & 7, ti = tid >> 3;
            const int d0 = td * 8;
            u64 a2[2][4];
#pragma unroll
            for (int q = 0; q < 2; q++)
#pragma unroll
                for (int h = 0; h < 4; h++) a2[q][h] = 0ull;
#pragma unroll 1
            for (int j = 0; j < JT; j++) {
#pragma unroll
                for (int e = 0; e < 5; e++) {
                    const float* mr = &sm[OFF_MSG + j*320 + e*64 + d0];
                    float4 ma = *(const float4*)mr;
                    float4 mb = *(const float4*)(mr + 4);
                    u64 m0 = pack2(ma.x,ma.y), m1 = pack2(ma.z,ma.w);
                    u64 m2 = pack2(mb.x,mb.y), m3 = pack2(mb.z,mb.w);
                    const float* sc = &sm[OFF_SSC + ti*2*161 + j*5 + e];
#pragma unroll
                    for (int q = 0; q < 2; q++) {
                        float s = sc[q*161];
                        u64 ss = pack2(s,s);
                        a2[q][0] = fma2(ss, m0, a2[q][0]);
                        a2[q][1] = fma2(ss, m1, a2[q][1]);
                        a2[q][2] = fma2(ss, m2, a2[q][2]);
                        a2[q][3] = fma2(ss, m3, a2[q][3]);
                    }
                }
            }
#pragma unroll
            for (int q = 0; q < 2; q++) {
                float v[8];
                unpack2(a2[q][0], v[0], v[1]); unpack2(a2[q][1], v[2], v[3]);
                unpack2(a2[q][2], v[4], v[5]); unpack2(a2[q][3], v[6], v[7]);
                float* dst = &g_part[js][b*Nn + ti*2 + q][d0];
                *(float4*)dst       = make_float4(v[0],v[1],v[2],v[3]);
                *(float4*)(dst + 4) = make_float4(v[4],v[5],v[6],v[7]);
            }
            grid_bar();
        }
    }
}

extern "C" void kernel_launch(void* const* d_in, const int* in_sizes, int n_in,
                              void* d_out, int out_size) {
    const float* inputs = (const float*)d_in[0];
    const int*   mask   = (const int*)  d_in[1];
    const float* We     = (const float*)d_in[2];
    const float* be     = (const float*)d_in[3];
    const float* Wa     = (const float*)d_in[4];
    const float* ba     = (const float*)d_in[5];
    const float* Wr     = (const float*)d_in[6];
    const float* br     = (const float*)d_in[7];
    const float* Wz     = (const float*)d_in[8];
    const float* bz     = (const float*)d_in[9];
    const float* Wh     = (const float*)d_in[10];
    const float* bh     = (const float*)d_in[11];
    float* out = (float*)d_out;

    static int configured = 0;
    if (!configured) {
        cudaFuncSetAttribute(grrn, cudaFuncAttributeMaxDynamicSharedMemorySize,
                             SMEM_FLOATS * 4);
        configured = 1;
    }
    grrn<<<GRID, THREADS, SMEM_FLOATS * 4>>>(inputs, mask, We, be, Wa, ba,
                                             Wr, br, Wz, bz, Wh, bh, out);
}

// round 8
// speedup vs baseline: 1.9364x; 1.0620x over previous
#include <cuda_runtime.h>

#define Bb 32
#define Nn 128
#define Dd 64
#define Ee 5
#define T_ITERS 6
#define GRID 128
#define THREADS 512
#define ROWS 32
#define JS 4
#define JT 32

// ---- smem float offsets (phase 1) ----
#define OFF_WR   0        // 8192
#define OFF_WZ   8192     // 8192
#define OFF_WH   16384    // 8192
#define OFF_WE   24576    // 20480
#define OFF_WA   45056    // 640
#define OFF_SA   45696    // 32*68 merged
#define OFF_SP   47872    // 32*68 prop (persists across iterations)
#define OFF_SH2  50048    // 32*68 r*prop
#define OFF_SCR0 52224    // 128*20
#define OFF_SCR1 54784    // 128*20
#define SMEM_FLOATS 57344
// ---- phase-2 overlay (weights region is dead there; restaged next iter) ----
#define OFF_MSG  0        // 32*320
#define OFF_SSC  10240    // 128*161
#define OFF_SROW 30848    // 640
#define OFF_SCOL 31488    // 160
#define OFF_MASK 31648    // 128*32

__device__ float g_rowg[Bb*Nn*Ee];
__device__ float g_colba[Bb*Nn*Ee];
__device__ float g_part[JS][Bb*Nn][Dd];

typedef unsigned long long u64;

__device__ __forceinline__ u64 pack2(float a, float b) {
    u64 r; asm("mov.b64 %0, {%1,%2};" : "=l"(r) : "f"(a), "f"(b)); return r;
}
__device__ __forceinline__ void unpack2(u64 v, float& a, float& b) {
    float x, y; asm("mov.b64 {%0,%1}, %2;" : "=f"(x), "=f"(y) : "l"(v));
    a = x; b = y;
}
__device__ __forceinline__ u64 fma2(u64 a, u64 b, u64 c) {
    u64 d; asm("fma.rn.f32x2 %0, %1, %2, %3;" : "=l"(d) : "l"(a), "l"(b), "l"(c)); return d;
}
__device__ __forceinline__ u64 add2(u64 a, u64 b) {
    u64 d; asm("add.rn.f32x2 %0, %1, %2;" : "=l"(d) : "l"(a), "l"(b)); return d;
}
__device__ __forceinline__ float sigf(float x) {
    return __fdividef(1.0f, 1.0f + __expf(-x));
}
__device__ __forceinline__ float tanhff(float x) {
    return fmaf(2.0f, sigf(2.0f * x), -1.0f);
}
__device__ __forceinline__ unsigned cvta_smem(const void* p) {
    return (unsigned)__cvta_generic_to_shared(p);
}
__device__ __forceinline__ void cpa16(unsigned dst, const void* src) {
    asm volatile("cp.async.ca.shared.global [%0], [%1], 16;" :: "r"(dst), "l"(src));
}
#define CP_COMMIT  asm volatile("cp.async.commit_group;" ::: "memory")
#define CP_WAIT(n) asm volatile("cp.async.wait_group %0;" :: "n"(n) : "memory")

// cluster-wide barrier: arrive(release) + wait(acquire) at cluster scope.
// Replaces the grid-wide sense-reversing barrier: all producer/consumer
// traffic (g_rowg/g_colba/g_part) is within the 4-CTA (b, js) cluster.
__device__ __forceinline__ void cluster_bar() {
    asm volatile("barrier.cluster.arrive.aligned;" ::: "memory");
    asm volatile("barrier.cluster.wait.aligned;" ::: "memory");
}

// scratch: slot stride 20 floats (16 used, 16B-aligned, conflict-spread)
__device__ __forceinline__ void scr_w(float* sm, int base, int slot, const u64 a[4][2]) {
#pragma unroll
    for (int r = 0; r < 4; r++) {
        float x, y, z, w;
        unpack2(a[r][0], x, y); unpack2(a[r][1], z, w);
        *(float4*)&sm[base + slot*20 + r*4] = make_float4(x, y, z, w);
    }
}
__device__ __forceinline__ void scr_a(float* sm, int base, int slot, u64 a[4][2]) {
#pragma unroll
    for (int r = 0; r < 4; r++) {
        float4 v = *(const float4*)&sm[base + slot*20 + r*4];
        a[r][0] = add2(a[r][0], pack2(v.x, v.y));
        a[r][1] = add2(a[r][1], pack2(v.z, v.w));
    }
}

// dual-gate quarter GEMM: 4 rows x 4f over 32 k (shared act loads)
__device__ __forceinline__ void gate_q2(const float* sm, int wb1, int wb2,
                                        int abase, int koff, int kg, int rg, int f0,
                                        u64 ar[4][2], u64 az[4][2]) {
#pragma unroll 2
    for (int s4 = 0; s4 < 32; s4 += 4) {
        float av[4][4];
#pragma unroll
        for (int r = 0; r < 4; r++) {
            float4 tv = *(const float4*)&sm[abase + (rg*4+r)*68 + koff + s4];
            av[r][0]=tv.x; av[r][1]=tv.y; av[r][2]=tv.z; av[r][3]=tv.w;
        }
#pragma unroll
        for (int u = 0; u < 4; u++) {
            int k = kg + s4 + u;
            float4 w1 = *(const float4*)&sm[wb1 + k*64 + f0];
            float4 w2 = *(const float4*)&sm[wb2 + k*64 + f0];
            u64 a01 = pack2(w1.x,w1.y), a23 = pack2(w1.z,w1.w);
            u64 b01 = pack2(w2.x,w2.y), b23 = pack2(w2.z,w2.w);
#pragma unroll
            for (int r = 0; r < 4; r++) {
                u64 aa = pack2(av[r][u], av[r][u]);
                ar[r][0] = fma2(aa, a01, ar[r][0]);
                ar[r][1] = fma2(aa, a23, ar[r][1]);
                az[r][0] = fma2(aa, b01, az[r][0]);
                az[r][1] = fma2(aa, b23, az[r][1]);
            }
        }
    }
}

// single-gate quarter GEMM
__device__ __forceinline__ void gate_q1(const float* sm, int wb,
                                        int abase, int koff, int kg, int rg, int f0,
                                        u64 ah[4][2]) {
#pragma unroll 2
    for (int s4 = 0; s4 < 32; s4 += 4) {
        float av[4][4];
#pragma unroll
        for (int r = 0; r < 4; r++) {
            float4 tv = *(const float4*)&sm[abase + (rg*4+r)*68 + koff + s4];
            av[r][0]=tv.x; av[r][1]=tv.y; av[r][2]=tv.z; av[r][3]=tv.w;
        }
#pragma unroll
        for (int u = 0; u < 4; u++) {
            int k = kg + s4 + u;
            float4 w1 = *(const float4*)&sm[wb + k*64 + f0];
            u64 a01 = pack2(w1.x,w1.y), a23 = pack2(w1.z,w1.w);
#pragma unroll
            for (int r = 0; r < 4; r++) {
                u64 aa = pack2(av[r][u], av[r][u]);
                ah[r][0] = fma2(aa, a01, ah[r][0]);
                ah[r][1] = fma2(aa, a23, ah[r][1]);
            }
        }
    }
}

// msg partial: NE experts x 4 rows x 4f over a 32-d half
template<int NE, int EB>
__device__ __forceinline__ void msg_core(const float* sm, int rg, int f0, int dbase,
                                         u64 m[3][4][2]) {
#pragma unroll 2
    for (int d4 = 0; d4 < 32; d4 += 4) {
        float av[4][4];
#pragma unroll
        for (int r = 0; r < 4; r++) {
            float4 tv = *(const float4*)&sm[OFF_SP + (rg*4+r)*68 + dbase + d4];
            av[r][0]=tv.x; av[r][1]=tv.y; av[r][2]=tv.z; av[r][3]=tv.w;
        }
#pragma unroll
        for (int u = 0; u < 4; u++) {
            int d = dbase + d4 + u;
#pragma unroll
            for (int e = 0; e < NE; e++) {
                float4 w = *(const float4*)&sm[OFF_WE + (EB+e)*4096 + d*64 + f0];
                u64 w01 = pack2(w.x,w.y), w23 = pack2(w.z,w.w);
#pragma unroll
                for (int r = 0; r < 4; r++) {
                    u64 aa = pack2(av[r][u], av[r][u]);
                    m[e][r][0] = fma2(aa, w01, m[e][r][0]);
                    m[e][r][1] = fma2(aa, w23, m[e][r][1]);
                }
            }
        }
    }
}

template<int NE, int EB>
__device__ __forceinline__ void msg_out(float* sm, int rg, int f0, int fg, int r0,
                                        const float* __restrict__ ba, u64 m[3][4][2]) {
#pragma unroll
    for (int e = 0; e < NE; e++) {
        float bav = __ldg(&ba[EB+e]);
#pragma unroll
        for (int r = 0; r < 4; r++) {
            float v0,v1,v2,v3;
            unpack2(m[e][r][0], v0, v1); unpack2(m[e][r][1], v2, v3);
            int row = rg*4 + r;
            *(float4*)&sm[OFF_MSG + row*320 + (EB+e)*64 + f0] = make_float4(v0,v1,v2,v3);
            const float* wa = &sm[OFF_WA + (EB+e)*128 + f0];
            float rowp = v0*wa[0]; rowp = fmaf(v1,wa[1],rowp);
            rowp = fmaf(v2,wa[2],rowp); rowp = fmaf(v3,wa[3],rowp);
            float colp = v0*wa[64]; colp = fmaf(v1,wa[65],colp);
            colp = fmaf(v2,wa[66],colp); colp = fmaf(v3,wa[67],colp);
#pragma unroll
            for (int o = 8; o > 0; o >>= 1) {
                rowp += __shfl_down_sync(0xffffffffu, rowp, o, 16);
                colp += __shfl_down_sync(0xffffffffu, colp, o, 16);
            }
            if (fg == 0) {
                g_rowg[(r0+row)*5 + EB+e]  = rowp;
                g_colba[(r0+row)*5 + EB+e] = colp + bav;
            }
        }
    }
}

extern "C" __global__ void __cluster_dims__(4, 1, 1) __launch_bounds__(THREADS)
grrn(const float* __restrict__ inputs, const int* __restrict__ mask,
     const float* __restrict__ We, const float* __restrict__ be,
     const float* __restrict__ Wa, const float* __restrict__ ba,
     const float* __restrict__ Wr, const float* __restrict__ br,
     const float* __restrict__ Wz, const float* __restrict__ bz,
     const float* __restrict__ Wh, const float* __restrict__ bh,
     float* __restrict__ out)
{
    extern __shared__ float sm[];
    const int tid  = threadIdx.x;
    const int blk  = blockIdx.x;
    const int r0   = blk * ROWS;
    const int b    = blk >> 2;
    const int js   = blk & 3;       // == cluster rank
    const int j0   = js * JT;
    const int fg   = tid & 15;
    const int f0   = fg * 4;
    const int rg   = (tid >> 4) & 7;
    const int ks   = tid >> 7;
    const int slot = tid & 127;
    const unsigned sb = cvta_smem(sm);

    for (int t = 0; t < T_ITERS; t++) {
        // ---- stage weights: G1=(Wr,Wz) G2=(Wh) G3=(We,Wa) ----
        for (int i = tid; i < 2048; i += THREADS) {
            cpa16(sb + OFF_WR*4 + i*16, Wr + 4*i);
            cpa16(sb + OFF_WZ*4 + i*16, Wz + 4*i);
        }
        CP_COMMIT;
        for (int i = tid; i < 2048; i += THREADS)
            cpa16(sb + OFF_WH*4 + i*16, Wh + 4*i);
        CP_COMMIT;
        for (int i = tid; i < 5120; i += THREADS)
            cpa16(sb + OFF_WE*4 + i*16, We + 4*i);
        if (tid < 160) cpa16(sb + OFF_WA*4 + tid*16, Wa + 4*tid);
        CP_COMMIT;

        if (t == 0) {
            int rr = tid >> 4;
            float4 p = *(const float4*)&inputs[(size_t)(r0 + rr)*Dd + f0];
            *(float4*)&sm[OFF_SP + rr*68 + f0] = p;
            CP_WAIT(0);
            __syncthreads();
        } else {
            // merged = sum of 4 partials
            {
                int rr = tid >> 4;
                float4 msum = make_float4(0.f,0.f,0.f,0.f);
#pragma unroll
                for (int p = 0; p < JS; p++) {
                    float4 a = __ldcg((const float4*)&g_part[p][r0 + rr][f0]);
                    msum.x += a.x; msum.y += a.y; msum.z += a.z; msum.w += a.w;
                }
                *(float4*)&sm[OFF_SA + rr*68 + f0] = msum;
            }
            CP_WAIT(2);          // G1 (Wr,Wz) done
            __syncthreads();

            // ---- rz gates: k-quarter per ks ----
            u64 ar[4][2], az[4][2];
            if (ks == 0) {
                float4 brv = __ldg((const float4*)&br[f0]);
                float4 bzv = __ldg((const float4*)&bz[f0]);
#pragma unroll
                for (int r = 0; r < 4; r++) {
                    ar[r][0] = pack2(brv.x,brv.y); ar[r][1] = pack2(brv.z,brv.w);
                    az[r][0] = pack2(bzv.x,bzv.y); az[r][1] = pack2(bzv.z,bzv.w);
                }
            } else {
#pragma unroll
                for (int r = 0; r < 4; r++)
                    ar[r][0]=ar[r][1]=az[r][0]=az[r][1]=0ull;
            }
            {
                const int abase = (ks < 2) ? OFF_SA : OFF_SP;
                const int koff  = (ks & 1) * 32;
                const int kg    = ks * 32;
                gate_q2(sm, OFF_WR, OFF_WZ, abase, koff, kg, rg, f0, ar, az);
            }
            if (ks == 2) scr_w(sm, OFF_SCR0, slot, ar);
            if (ks == 3) scr_w(sm, OFF_SCR1, slot, az);
            __syncthreads();
            if (ks == 0) scr_a(sm, OFF_SCR0, slot, ar);
            if (ks == 1) scr_a(sm, OFF_SCR1, slot, az);
            __syncthreads();
            if (ks == 3) scr_w(sm, OFF_SCR0, slot, ar);
            if (ks == 2) scr_w(sm, OFF_SCR1, slot, az);
            __syncthreads();
            if (ks == 0) scr_a(sm, OFF_SCR0, slot, ar);
            if (ks == 1) scr_a(sm, OFF_SCR1, slot, az);
            __syncthreads();
            if (ks == 1) scr_w(sm, OFF_SCR0, slot, ar);
            if (ks == 0) scr_w(sm, OFF_SCR1, slot, az);
            __syncthreads();

            float zq[4][4];
            if (ks == 0) {
                scr_a(sm, OFF_SCR0, slot, ar);
#pragma unroll
                for (int r = 0; r < 4; r++) {
                    float x0,x1,x2,x3;
                    unpack2(ar[r][0], x0, x1); unpack2(ar[r][1], x2, x3);
                    int row = rg*4 + r;
                    const float* pp = &sm[OFF_SP + row*68 + f0];
                    float* sh = &sm[OFF_SH2 + row*68 + f0];
                    sh[0] = sigf(x0)*pp[0]; sh[1] = sigf(x1)*pp[1];
                    sh[2] = sigf(x2)*pp[2]; sh[3] = sigf(x3)*pp[3];
                }
            }
            if (ks == 1) {
                scr_a(sm, OFF_SCR1, slot, az);
#pragma unroll
                for (int r = 0; r < 4; r++) {
                    float x0,x1,x2,x3;
                    unpack2(az[r][0], x0, x1); unpack2(az[r][1], x2, x3);
                    zq[r][0]=sigf(x0); zq[r][1]=sigf(x1);
                    zq[r][2]=sigf(x2); zq[r][3]=sigf(x3);
                }
            }
            __syncthreads();

            // ---- h gate ----
            CP_WAIT(1);          // G2 (Wh) done
            u64 ah[4][2];
            if (ks == 0) {
                float4 bhv = __ldg((const float4*)&bh[f0]);
#pragma unroll
                for (int r = 0; r < 4; r++) {
                    ah[r][0] = pack2(bhv.x,bhv.y); ah[r][1] = pack2(bhv.z,bhv.w);
                }
            } else {
#pragma unroll
                for (int r = 0; r < 4; r++) ah[r][0]=ah[r][1]=0ull;
            }
            {
                const int hbase = (ks < 2) ? OFF_SA : OFF_SH2;
                const int koff  = (ks & 1) * 32;
                const int kg    = ks * 32;
                gate_q1(sm, OFF_WH, hbase, koff, kg, rg, f0, ah);
            }
            if (ks == 1) scr_w(sm, OFF_SCR0, slot, ah);
            if (ks == 2) scr_w(sm, OFF_SCR1, slot, ah);
            __syncthreads();
            if (ks == 0) { scr_a(sm, OFF_SCR0, slot, ah); scr_a(sm, OFF_SCR1, slot, ah); }
            __syncthreads();
            if (ks == 3) scr_w(sm, OFF_SCR0, slot, ah);
            if (ks == 1) {
#pragma unroll
                for (int r = 0; r < 4; r++)
                    *(float4*)&sm[OFF_SCR1 + slot*20 + r*4] =
                        make_float4(zq[r][0], zq[r][1], zq[r][2], zq[r][3]);
            }
            CP_WAIT(0);          // G3 (We, Wa) done
            __syncthreads();
            if (ks == 0) {
                scr_a(sm, OFF_SCR0, slot, ah);
#pragma unroll
                for (int r = 0; r < 4; r++) {
                    float h0,h1,h2,h3;
                    unpack2(ah[r][0], h0, h1); unpack2(ah[r][1], h2, h3);
                    float4 zv = *(const float4*)&sm[OFF_SCR1 + slot*20 + r*4];
                    int row = rg*4 + r;
                    float4 pv = *(const float4*)&sm[OFF_SP + row*68 + f0];
                    float4 np;
                    np.x = fmaf(zv.x, tanhff(h0) - pv.x, pv.x);
                    np.y = fmaf(zv.y, tanhff(h1) - pv.y, pv.y);
                    np.z = fmaf(zv.z, tanhff(h2) - pv.z, pv.z);
                    np.w = fmaf(zv.w, tanhff(h3) - pv.w, pv.w);
                    *(float4*)&sm[OFF_SP + row*68 + f0] = np;
                }
            }
            __syncthreads();
        }

        // ---- msg GEMM: (eg,dg) split ----
        u64 m[3][4][2];
        const int eg = ks >> 1;
        const int dbase = (ks & 1) * 32;
        if (eg == 0) {
            if ((ks & 1) == 0) {
#pragma unroll
                for (int e = 0; e < 3; e++) {
                    float4 bev = __ldg((const float4*)&be[e*64 + f0]);
#pragma unroll
                    for (int r = 0; r < 4; r++) {
                        m[e][r][0] = pack2(bev.x,bev.y); m[e][r][1] = pack2(bev.z,bev.w);
                    }
                }
            } else {
#pragma unroll
                for (int e = 0; e < 3; e++)
#pragma unroll
                    for (int r = 0; r < 4; r++) m[e][r][0]=m[e][r][1]=0ull;
            }
            msg_core<3,0>(sm, rg, f0, dbase, m);
        } else {
            if ((ks & 1) == 0) {
#pragma unroll
                for (int e = 0; e < 2; e++) {
                    float4 bev = __ldg((const float4*)&be[(3+e)*64 + f0]);
#pragma unroll
                    for (int r = 0; r < 4; r++) {
                        m[e][r][0] = pack2(bev.x,bev.y); m[e][r][1] = pack2(bev.z,bev.w);
                    }
                }
            } else {
#pragma unroll
                for (int e = 0; e < 2; e++)
#pragma unroll
                    for (int r = 0; r < 4; r++) m[e][r][0]=m[e][r][1]=0ull;
            }
            msg_core<2,3>(sm, rg, f0, dbase, m);
        }
        if (ks == 1) scr_w(sm, OFF_SCR0, slot, m[0]);
        if (ks == 3) scr_w(sm, OFF_SCR1, slot, m[0]);
        __syncthreads();
        if (ks == 0) scr_a(sm, OFF_SCR0, slot, m[0]);
        if (ks == 2) scr_a(sm, OFF_SCR1, slot, m[0]);
        __syncthreads();
        if (ks == 1) scr_w(sm, OFF_SCR0, slot, m[1]);
        if (ks == 3) scr_w(sm, OFF_SCR1, slot, m[1]);
        __syncthreads();
        if (ks == 0) scr_a(sm, OFF_SCR0, slot, m[1]);
        if (ks == 2) scr_a(sm, OFF_SCR1, slot, m[1]);
        __syncthreads();
        if (ks == 1) scr_w(sm, OFF_SCR0, slot, m[2]);
        __syncthreads();
        if (ks == 0) {
            scr_a(sm, OFF_SCR0, slot, m[2]);
            msg_out<3,0>(sm, rg, f0, fg, r0, ba, m);
        }
        if (ks == 2) msg_out<2,3>(sm, rg, f0, fg, r0, ba, m);
        cluster_bar();

        // ================= PHASE 2: scores + merged =================
        for (int i = tid; i < 640; i += THREADS)
            sm[OFF_SROW + i] = __ldcg(&g_rowg[b*640 + i]);
        for (int i = tid; i < 160; i += THREADS)
            sm[OFF_SCOL + i] = __ldcg(&g_colba[(b*Nn + j0)*5 + i]);
        for (int i = tid; i < 1024; i += THREADS) {
            int irow = i >> 3, seg = i & 7;
            int4 mv = __ldg((const int4*)&mask[(size_t)(b*Nn + irow)*Nn + j0 + seg*4]);
            float* dst = &sm[OFF_MASK + irow*32 + seg*4];
            dst[0] = (float)mv.x; dst[1] = (float)mv.y;
            dst[2] = (float)mv.z; dst[3] = (float)mv.w;
        }
        __syncthreads();

        float* outB = out + (size_t)(t*Bb + b)*(Nn*Nn*Ee) + (size_t)j0*Ee;
#pragma unroll 4
        for (int p = 0; p < 40; p++) {
            int idx = p*512 + tid;
            int i = idx / 160;
            int r = idx - i*160;
            int j = r / 5;
            float x = sm[OFF_SROW + i*5 + (r - j*5)] + sm[OFF_SCOL + r];
            float s = sm[OFF_MASK + i*32 + j] * __fdividef(1.0f, 1.0f + __expf(-x));
            sm[OFF_SSC + i*161 + r] = s;
            outB[(size_t)i*(Nn*Ee) + r] = s;
        }

        if (t < T_ITERS - 1) {
            __syncthreads();
            const int td = tid & 7, ti = tid >> 3;
            const int d0 = td * 8;
            u64 a2[2][4];
#pragma unroll
            for (int q = 0; q < 2; q++)
#pragma unroll
                for (int h = 0; h < 4; h++) a2[q][h] = 0ull;
#pragma unroll 1
            for (int j = 0; j < JT; j++) {
#pragma unroll
                for (int e = 0; e < 5; e++) {
                    const float* mr = &sm[OFF_MSG + j*320 + e*64 + d0];
                    float4 ma = *(const float4*)mr;
                    float4 mb = *(const float4*)(mr + 4);
                    u64 m0 = pack2(ma.x,ma.y), m1 = pack2(ma.z,ma.w);
                    u64 m2 = pack2(mb.x,mb.y), m3 = pack2(mb.z,mb.w);
                    const float* sc = &sm[OFF_SSC + ti*2*161 + j*5 + e];
#pragma unroll
                    for (int q = 0; q < 2; q++) {
                        float s = sc[q*161];
                        u64 ss = pack2(s,s);
                        a2[q][0] = fma2(ss, m0, a2[q][0]);
                        a2[q][1] = fma2(ss, m1, a2[q][1]);
                        a2[q][2] = fma2(ss, m2, a2[q][2]);
                        a2[q][3] = fma2(ss, m3, a2[q][3]);
                    }
                }
            }
#pragma unroll
            for (int q = 0; q < 2; q++) {
                float v[8];
                unpack2(a2[q][0], v[0], v[1]); unpack2(a2[q][1], v[2], v[3]);
                unpack2(a2[q][2], v[4], v[5]); unpack2(a2[q][3], v[6], v[7]);
                float* dst = &g_part[js][b*Nn + ti*2 + q][d0];
                *(float4*)dst       = make_float4(v[0],v[1],v[2],v[3]);
                *(float4*)(dst + 4) = make_float4(v[4],v[5],v[6],v[7]);
            }
            cluster_bar();
        }
    }
}

extern "C" void kernel_launch(void* const* d_in, const int* in_sizes, int n_in,
                              void* d_out, int out_size) {
    const float* inputs = (const float*)d_in[0];
    const int*   mask   = (const int*)  d_in[1];
    const float* We     = (const float*)d_in[2];
    const float* be     = (const float*)d_in[3];
    const float* Wa     = (const float*)d_in[4];
    const float* ba     = (const float*)d_in[5];
    const float* Wr     = (const float*)d_in[6];
    const float* br     = (const float*)d_in[7];
    const float* Wz     = (const float*)d_in[8];
    const float* bz     = (const float*)d_in[9];
    const float* Wh     = (const float*)d_in[10];
    const float* bh     = (const float*)d_in[11];
    float* out = (float*)d_out;

    static int configured = 0;
    if (!configured) {
        cudaFuncSetAttribute(grrn, cudaFuncAttributeMaxDynamicSharedMemorySize,
                             SMEM_FLOATS * 4);
        configured = 1;
    }
    grrn<<<GRID, THREADS, SMEM_FLOATS * 4>>>(inputs, mask, We, be, Wa, ba,
                                             Wr, br, Wz, bz, Wh, bh, out);
}

// round 9
// speedup vs baseline: 2.6884x; 1.3884x over previous
#include <cuda_runtime.h>

#define Bb 32
#define Nn 128
#define Dd 64
#define Ee 5
#define T_ITERS 6
#define GRID 128
#define THREADS 512
#define ROWS 32
#define JS 4
#define JT 32

// ---- smem float offsets (phase 1) ----
#define OFF_WR   0        // 8192
#define OFF_WZ   8192     // 8192
#define OFF_WH   16384    // 8192
#define OFF_WE   24576    // 20480
#define OFF_WA   45056    // 640
#define OFF_SA   45696    // 32*68 merged
#define OFF_SP   47872    // 32*68 prop (persists across iterations)
#define OFF_SH2  50048    // 32*68 r*prop
#define OFF_SCR0 52224    // 128*20
#define OFF_SCR1 54784    // 128*20
#define SMEM_FLOATS 57344
// ---- phase-2 overlay ----
#define OFF_MSG  0        // 32*320  (split-half layout per (row,e))
#define OFF_SSC  10240    // 128*161
#define OFF_SROW 30848    // 640
#define OFF_SCOL 31488    // 160
#define OFF_MASK 31648    // 128*32

__device__ float g_rowg[Bb*Nn*Ee];
__device__ float g_colba[Bb*Nn*Ee];
__device__ float g_part[2*JS][Bb*Nn][Dd];   // js*2 + k-half

typedef unsigned long long u64;

__device__ __forceinline__ u64 pack2(float a, float b) {
    u64 r; asm("mov.b64 %0, {%1,%2};" : "=l"(r) : "f"(a), "f"(b)); return r;
}
__device__ __forceinline__ void unpack2(u64 v, float& a, float& b) {
    float x, y; asm("mov.b64 {%0,%1}, %2;" : "=f"(x), "=f"(y) : "l"(v));
    a = x; b = y;
}
__device__ __forceinline__ u64 fma2(u64 a, u64 b, u64 c) {
    u64 d; asm("fma.rn.f32x2 %0, %1, %2, %3;" : "=l"(d) : "l"(a), "l"(b), "l"(c)); return d;
}
__device__ __forceinline__ u64 add2(u64 a, u64 b) {
    u64 d; asm("add.rn.f32x2 %0, %1, %2;" : "=l"(d) : "l"(a), "l"(b)); return d;
}
__device__ __forceinline__ float sigf(float x) {
    return __fdividef(1.0f, 1.0f + __expf(-x));
}
__device__ __forceinline__ float tanhff(float x) {
    return fmaf(2.0f, sigf(2.0f * x), -1.0f);
}
__device__ __forceinline__ unsigned cvta_smem(const void* p) {
    return (unsigned)__cvta_generic_to_shared(p);
}
__device__ __forceinline__ void cpa16(unsigned dst, const void* src) {
    asm volatile("cp.async.ca.shared.global [%0], [%1], 16;" :: "r"(dst), "l"(src));
}
#define CP_COMMIT  asm volatile("cp.async.commit_group;" ::: "memory")
#define CP_WAIT(n) asm volatile("cp.async.wait_group %0;" :: "n"(n) : "memory")

__device__ __forceinline__ void cluster_bar() {
    asm volatile("barrier.cluster.arrive.aligned;" ::: "memory");
    asm volatile("barrier.cluster.wait.aligned;" ::: "memory");
}

// scratch: slot stride 20 floats
__device__ __forceinline__ void scr_w(float* sm, int base, int slot, const u64 a[4][2]) {
#pragma unroll
    for (int r = 0; r < 4; r++) {
        float x, y, z, w;
        unpack2(a[r][0], x, y); unpack2(a[r][1], z, w);
        *(float4*)&sm[base + slot*20 + r*4] = make_float4(x, y, z, w);
    }
}
__device__ __forceinline__ void scr_a(float* sm, int base, int slot, u64 a[4][2]) {
#pragma unroll
    for (int r = 0; r < 4; r++) {
        float4 v = *(const float4*)&sm[base + slot*20 + r*4];
        a[r][0] = add2(a[r][0], pack2(v.x, v.y));
        a[r][1] = add2(a[r][1], pack2(v.z, v.w));
    }
}

__device__ __forceinline__ void gate_q2(const float* sm, int wb1, int wb2,
                                        int abase, int koff, int kg, int rg, int f0,
                                        u64 ar[4][2], u64 az[4][2]) {
#pragma unroll 2
    for (int s4 = 0; s4 < 32; s4 += 4) {
        float av[4][4];
#pragma unroll
        for (int r = 0; r < 4; r++) {
            float4 tv = *(const float4*)&sm[abase + (rg*4+r)*68 + koff + s4];
            av[r][0]=tv.x; av[r][1]=tv.y; av[r][2]=tv.z; av[r][3]=tv.w;
        }
#pragma unroll
        for (int u = 0; u < 4; u++) {
            int k = kg + s4 + u;
            float4 w1 = *(const float4*)&sm[wb1 + k*64 + f0];
            float4 w2 = *(const float4*)&sm[wb2 + k*64 + f0];
            u64 a01 = pack2(w1.x,w1.y), a23 = pack2(w1.z,w1.w);
            u64 b01 = pack2(w2.x,w2.y), b23 = pack2(w2.z,w2.w);
#pragma unroll
            for (int r = 0; r < 4; r++) {
                u64 aa = pack2(av[r][u], av[r][u]);
                ar[r][0] = fma2(aa, a01, ar[r][0]);
                ar[r][1] = fma2(aa, a23, ar[r][1]);
                az[r][0] = fma2(aa, b01, az[r][0]);
                az[r][1] = fma2(aa, b23, az[r][1]);
            }
        }
    }
}

__device__ __forceinline__ void gate_q1(const float* sm, int wb,
                                        int abase, int koff, int kg, int rg, int f0,
                                        u64 ah[4][2]) {
#pragma unroll 2
    for (int s4 = 0; s4 < 32; s4 += 4) {
        float av[4][4];
#pragma unroll
        for (int r = 0; r < 4; r++) {
            float4 tv = *(const float4*)&sm[abase + (rg*4+r)*68 + koff + s4];
            av[r][0]=tv.x; av[r][1]=tv.y; av[r][2]=tv.z; av[r][3]=tv.w;
        }
#pragma unroll
        for (int u = 0; u < 4; u++) {
            int k = kg + s4 + u;
            float4 w1 = *(const float4*)&sm[wb + k*64 + f0];
            u64 a01 = pack2(w1.x,w1.y), a23 = pack2(w1.z,w1.w);
#pragma unroll
            for (int r = 0; r < 4; r++) {
                u64 aa = pack2(av[r][u], av[r][u]);
                ah[r][0] = fma2(aa, a01, ah[r][0]);
                ah[r][1] = fma2(aa, a23, ah[r][1]);
            }
        }
    }
}

template<int NE, int EB>
__device__ __forceinline__ void msg_core(const float* sm, int rg, int f0, int dbase,
                                         u64 m[3][4][2]) {
#pragma unroll 2
    for (int d4 = 0; d4 < 32; d4 += 4) {
        float av[4][4];
#pragma unroll
        for (int r = 0; r < 4; r++) {
            float4 tv = *(const float4*)&sm[OFF_SP + (rg*4+r)*68 + dbase + d4];
            av[r][0]=tv.x; av[r][1]=tv.y; av[r][2]=tv.z; av[r][3]=tv.w;
        }
#pragma unroll
        for (int u = 0; u < 4; u++) {
            int d = dbase + d4 + u;
#pragma unroll
            for (int e = 0; e < NE; e++) {
                float4 w = *(const float4*)&sm[OFF_WE + (EB+e)*4096 + d*64 + f0];
                u64 w01 = pack2(w.x,w.y), w23 = pack2(w.z,w.w);
#pragma unroll
                for (int r = 0; r < 4; r++) {
                    u64 aa = pack2(av[r][u], av[r][u]);
                    m[e][r][0] = fma2(aa, w01, m[e][r][0]);
                    m[e][r][1] = fma2(aa, w23, m[e][r][1]);
                }
            }
        }
    }
}

// msg writer: split-half layout — (row,e) row is [halfA d(8k..8k+3)][halfB d(8k+4..8k+7)]
template<int NE, int EB>
__device__ __forceinline__ void msg_out(float* sm, int rg, int f0, int fg, int r0,
                                        const float* __restrict__ ba, u64 m[3][4][2]) {
    const int moff = (fg & 1)*32 + (fg >> 1)*4;   // split-half position for f0 block
#pragma unroll
    for (int e = 0; e < NE; e++) {
        float bav = __ldg(&ba[EB+e]);
#pragma unroll
        for (int r = 0; r < 4; r++) {
            float v0,v1,v2,v3;
            unpack2(m[e][r][0], v0, v1); unpack2(m[e][r][1], v2, v3);
            int row = rg*4 + r;
            *(float4*)&sm[OFF_MSG + row*320 + (EB+e)*64 + moff] = make_float4(v0,v1,v2,v3);
            const float* wa = &sm[OFF_WA + (EB+e)*128 + f0];
            float rowp = v0*wa[0]; rowp = fmaf(v1,wa[1],rowp);
            rowp = fmaf(v2,wa[2],rowp); rowp = fmaf(v3,wa[3],rowp);
            float colp = v0*wa[64]; colp = fmaf(v1,wa[65],colp);
            colp = fmaf(v2,wa[66],colp); colp = fmaf(v3,wa[67],colp);
#pragma unroll
            for (int o = 8; o > 0; o >>= 1) {
                rowp += __shfl_down_sync(0xffffffffu, rowp, o, 16);
                colp += __shfl_down_sync(0xffffffffu, colp, o, 16);
            }
            if (fg == 0) {
                g_rowg[(r0+row)*5 + EB+e]  = rowp;
                g_colba[(r0+row)*5 + EB+e] = colp + bav;
            }
        }
    }
}

extern "C" __global__ void __cluster_dims__(4, 1, 1) __launch_bounds__(THREADS)
grrn(const float* __restrict__ inputs, const int* __restrict__ mask,
     const float* __restrict__ We, const float* __restrict__ be,
     const float* __restrict__ Wa, const float* __restrict__ ba,
     const float* __restrict__ Wr, const float* __restrict__ br,
     const float* __restrict__ Wz, const float* __restrict__ bz,
     const float* __restrict__ Wh, const float* __restrict__ bh,
     float* __restrict__ out)
{
    extern __shared__ float sm[];
    const int tid  = threadIdx.x;
    const int blk  = blockIdx.x;
    const int r0   = blk * ROWS;
    const int b    = blk >> 2;
    const int js   = blk & 3;
    const int j0   = js * JT;
    const int fg   = tid & 15;
    const int f0   = fg * 4;
    const int rg   = (tid >> 4) & 7;
    const int ks   = tid >> 7;
    const int slot = tid & 127;
    const unsigned sb = cvta_smem(sm);

    for (int t = 0; t < T_ITERS; t++) {
        // ---- stage weights: G1=(Wr,Wz) G2=(Wh) G3=(We,Wa) ----
        for (int i = tid; i < 2048; i += THREADS) {
            cpa16(sb + OFF_WR*4 + i*16, Wr + 4*i);
            cpa16(sb + OFF_WZ*4 + i*16, Wz + 4*i);
        }
        CP_COMMIT;
        for (int i = tid; i < 2048; i += THREADS)
            cpa16(sb + OFF_WH*4 + i*16, Wh + 4*i);
        CP_COMMIT;
        for (int i = tid; i < 5120; i += THREADS)
            cpa16(sb + OFF_WE*4 + i*16, We + 4*i);
        if (tid < 160) cpa16(sb + OFF_WA*4 + tid*16, Wa + 4*tid);
        CP_COMMIT;

        if (t == 0) {
            int rr = tid >> 4;
            float4 p = *(const float4*)&inputs[(size_t)(r0 + rr)*Dd + f0];
            *(float4*)&sm[OFF_SP + rr*68 + f0] = p;
            CP_WAIT(0);
            __syncthreads();
        } else {
            // merged = sum of 8 partials (4 js siblings x 2 k-halves)
            {
                int rr = tid >> 4;
                float4 msum = make_float4(0.f,0.f,0.f,0.f);
#pragma unroll
                for (int p = 0; p < 2*JS; p++) {
                    float4 a = __ldcg((const float4*)&g_part[p][r0 + rr][f0]);
                    msum.x += a.x; msum.y += a.y; msum.z += a.z; msum.w += a.w;
                }
                *(float4*)&sm[OFF_SA + rr*68 + f0] = msum;
            }
            CP_WAIT(2);
            __syncthreads();

            // ---- rz gates: k-quarter per ks ----
            u64 ar[4][2], az[4][2];
            if (ks == 0) {
                float4 brv = __ldg((const float4*)&br[f0]);
                float4 bzv = __ldg((const float4*)&bz[f0]);
#pragma unroll
                for (int r = 0; r < 4; r++) {
                    ar[r][0] = pack2(brv.x,brv.y); ar[r][1] = pack2(brv.z,brv.w);
                    az[r][0] = pack2(bzv.x,bzv.y); az[r][1] = pack2(bzv.z,bzv.w);
                }
            } else {
#pragma unroll
                for (int r = 0; r < 4; r++)
                    ar[r][0]=ar[r][1]=az[r][0]=az[r][1]=0ull;
            }
            {
                const int abase = (ks < 2) ? OFF_SA : OFF_SP;
                const int koff  = (ks & 1) * 32;
                const int kg    = ks * 32;
                gate_q2(sm, OFF_WR, OFF_WZ, abase, koff, kg, rg, f0, ar, az);
            }
            if (ks == 2) scr_w(sm, OFF_SCR0, slot, ar);
            if (ks == 3) scr_w(sm, OFF_SCR1, slot, az);
            __syncthreads();
            if (ks == 0) scr_a(sm, OFF_SCR0, slot, ar);
            if (ks == 1) scr_a(sm, OFF_SCR1, slot, az);
            __syncthreads();
            if (ks == 3) scr_w(sm, OFF_SCR0, slot, ar);
            if (ks == 2) scr_w(sm, OFF_SCR1, slot, az);
            __syncthreads();
            if (ks == 0) scr_a(sm, OFF_SCR0, slot, ar);
            if (ks == 1) scr_a(sm, OFF_SCR1, slot, az);
            __syncthreads();
            if (ks == 1) scr_w(sm, OFF_SCR0, slot, ar);
            if (ks == 0) scr_w(sm, OFF_SCR1, slot, az);
            __syncthreads();

            float zq[4][4];
            if (ks == 0) {
                scr_a(sm, OFF_SCR0, slot, ar);
#pragma unroll
                for (int r = 0; r < 4; r++) {
                    float x0,x1,x2,x3;
                    unpack2(ar[r][0], x0, x1); unpack2(ar[r][1], x2, x3);
                    int row = rg*4 + r;
                    const float* pp = &sm[OFF_SP + row*68 + f0];
                    float* sh = &sm[OFF_SH2 + row*68 + f0];
                    sh[0] = sigf(x0)*pp[0]; sh[1] = sigf(x1)*pp[1];
                    sh[2] = sigf(x2)*pp[2]; sh[3] = sigf(x3)*pp[3];
                }
            }
            if (ks == 1) {
                scr_a(sm, OFF_SCR1, slot, az);
#pragma unroll
                for (int r = 0; r < 4; r++) {
                    float x0,x1,x2,x3;
                    unpack2(az[r][0], x0, x1); unpack2(az[r][1], x2, x3);
                    zq[r][0]=sigf(x0); zq[r][1]=sigf(x1);
                    zq[r][2]=sigf(x2); zq[r][3]=sigf(x3);
                }
            }
            __syncthreads();

            // ---- h gate ----
            CP_WAIT(1);
            u64 ah[4][2];
            if (ks == 0) {
                float4 bhv = __ldg((const float4*)&bh[f0]);
#pragma unroll
                for (int r = 0; r < 4; r++) {
                    ah[r][0] = pack2(bhv.x,bhv.y); ah[r][1] = pack2(bhv.z,bhv.w);
                }
            } else {
#pragma unroll
                for (int r = 0; r < 4; r++) ah[r][0]=ah[r][1]=0ull;
            }
            {
                const int hbase = (ks < 2) ? OFF_SA : OFF_SH2;
                const int koff  = (ks & 1) * 32;
                const int kg    = ks * 32;
                gate_q1(sm, OFF_WH, hbase, koff, kg, rg, f0, ah);
            }
            if (ks == 1) scr_w(sm, OFF_SCR0, slot, ah);
            if (ks == 2) scr_w(sm, OFF_SCR1, slot, ah);
            __syncthreads();
            if (ks == 0) { scr_a(sm, OFF_SCR0, slot, ah); scr_a(sm, OFF_SCR1, slot, ah); }
            __syncthreads();
            if (ks == 3) scr_w(sm, OFF_SCR0, slot, ah);
            if (ks == 1) {
#pragma unroll
                for (int r = 0; r < 4; r++)
                    *(float4*)&sm[OFF_SCR1 + slot*20 + r*4] =
                        make_float4(zq[r][0], zq[r][1], zq[r][2], zq[r][3]);
            }
            CP_WAIT(0);
            __syncthreads();
            if (ks == 0) {
                scr_a(sm, OFF_SCR0, slot, ah);
#pragma unroll
                for (int r = 0; r < 4; r++) {
                    float h0,h1,h2,h3;
                    unpack2(ah[r][0], h0, h1); unpack2(ah[r][1], h2, h3);
                    float4 zv = *(const float4*)&sm[OFF_SCR1 + slot*20 + r*4];
                    int row = rg*4 + r;
                    float4 pv = *(const float4*)&sm[OFF_SP + row*68 + f0];
                    float4 np;
                    np.x = fmaf(zv.x, tanhff(h0) - pv.x, pv.x);
                    np.y = fmaf(zv.y, tanhff(h1) - pv.y, pv.y);
                    np.z = fmaf(zv.z, tanhff(h2) - pv.z, pv.z);
                    np.w = fmaf(zv.w, tanhff(h3) - pv.w, pv.w);
                    *(float4*)&sm[OFF_SP + row*68 + f0] = np;
                }
            }
            __syncthreads();
        }

        // ---- msg GEMM: (eg,dg) split ----
        u64 m[3][4][2];
        const int eg = ks >> 1;
        const int dbase = (ks & 1) * 32;
        if (eg == 0) {
            if ((ks & 1) == 0) {
#pragma unroll
                for (int e = 0; e < 3; e++) {
                    float4 bev = __ldg((const float4*)&be[e*64 + f0]);
#pragma unroll
                    for (int r = 0; r < 4; r++) {
                        m[e][r][0] = pack2(bev.x,bev.y); m[e][r][1] = pack2(bev.z,bev.w);
                    }
                }
            } else {
#pragma unroll
                for (int e = 0; e < 3; e++)
#pragma unroll
                    for (int r = 0; r < 4; r++) m[e][r][0]=m[e][r][1]=0ull;
            }
            msg_core<3,0>(sm, rg, f0, dbase, m);
        } else {
            if ((ks & 1) == 0) {
#pragma unroll
                for (int e = 0; e < 2; e++) {
                    float4 bev = __ldg((const float4*)&be[(3+e)*64 + f0]);
#pragma unroll
                    for (int r = 0; r < 4; r++) {
                        m[e][r][0] = pack2(bev.x,bev.y); m[e][r][1] = pack2(bev.z,bev.w);
                    }
                }
            } else {
#pragma unroll
                for (int e = 0; e < 2; e++)
#pragma unroll
                    for (int r = 0; r < 4; r++) m[e][r][0]=m[e][r][1]=0ull;
            }
            msg_core<2,3>(sm, rg, f0, dbase, m);
        }
        if (ks == 1) scr_w(sm, OFF_SCR0, slot, m[0]);
        if (ks == 3) scr_w(sm, OFF_SCR1, slot, m[0]);
        __syncthreads();
        if (ks == 0) scr_a(sm, OFF_SCR0, slot, m[0]);
        if (ks == 2) scr_a(sm, OFF_SCR1, slot, m[0]);
        __syncthreads();
        if (ks == 1) scr_w(sm, OFF_SCR0, slot, m[1]);
        if (ks == 3) scr_w(sm, OFF_SCR1, slot, m[1]);
        __syncthreads();
        if (ks == 0) scr_a(sm, OFF_SCR0, slot, m[1]);
        if (ks == 2) scr_a(sm, OFF_SCR1, slot, m[1]);
        __syncthreads();
        if (ks == 1) scr_w(sm, OFF_SCR0, slot, m[2]);
        __syncthreads();
        if (ks == 0) {
            scr_a(sm, OFF_SCR0, slot, m[2]);
            msg_out<3,0>(sm, rg, f0, fg, r0, ba, m);
        }
        if (ks == 2) msg_out<2,3>(sm, rg, f0, fg, r0, ba, m);
        cluster_bar();

        // ================= PHASE 2: scores + merged =================
        for (int i = tid; i < 640; i += THREADS)
            sm[OFF_SROW + i] = __ldcg(&g_rowg[b*640 + i]);
        for (int i = tid; i < 160; i += THREADS)
            sm[OFF_SCOL + i] = __ldcg(&g_colba[(b*Nn + j0)*5 + i]);
        for (int i = tid; i < 1024; i += THREADS) {
            int irow = i >> 3, seg = i & 7;
            int4 mv = __ldg((const int4*)&mask[(size_t)(b*Nn + irow)*Nn + j0 + seg*4]);
            float* dst = &sm[OFF_MASK + irow*32 + seg*4];
            dst[0] = (float)mv.x; dst[1] = (float)mv.y;
            dst[2] = (float)mv.z; dst[3] = (float)mv.w;
        }
        __syncthreads();

        float* outB = out + (size_t)(t*Bb + b)*(Nn*Nn*Ee) + (size_t)j0*Ee;
#pragma unroll 4
        for (int p = 0; p < 40; p++) {
            int idx = p*512 + tid;
            int i = idx / 160;
            int r = idx - i*160;
            int j = r / 5;
            float x = sm[OFF_SROW + i*5 + (r - j*5)] + sm[OFF_SCOL + r];
            float s = sm[OFF_MASK + i*32 + j] * __fdividef(1.0f, 1.0f + __expf(-x));
            sm[OFF_SSC + i*161 + r] = s;
            outB[(size_t)i*(Nn*Ee) + r] = s;
        }

        if (t < T_ITERS - 1) {
            __syncthreads();
            // merged: td8 x ti32(4 rows) x kh2 (k-half); split-half msg layout
            const int td = tid & 7;
            const int ti = (tid >> 3) & 31;
            const int kh = tid >> 8;          // 0/1: j-half of this block's JT window
            const int d0 = td * 8;
            u64 a2[4][4];
#pragma unroll
            for (int q = 0; q < 4; q++)
#pragma unroll
                for (int h = 0; h < 4; h++) a2[q][h] = 0ull;
#pragma unroll 1
            for (int j = 0; j < 16; j++) {
                int jj = kh*16 + j;
#pragma unroll
                for (int e = 0; e < 5; e++) {
                    const float* mr = &sm[OFF_MSG + jj*320 + e*64 + td*4];
                    float4 ma = *(const float4*)mr;          // d0..d0+3 (half A)
                    float4 mb = *(const float4*)(mr + 32);   // d0+4..d0+7 (half B)
                    u64 m0 = pack2(ma.x,ma.y), m1 = pack2(ma.z,ma.w);
                    u64 m2 = pack2(mb.x,mb.y), m3 = pack2(mb.z,mb.w);
                    const float* sc = &sm[OFF_SSC + (ti*4)*161 + jj*5 + e];
#pragma unroll
                    for (int q = 0; q < 4; q++) {
                        float s = sc[q*161];
                        u64 ss = pack2(s,s);
                        a2[q][0] = fma2(ss, m0, a2[q][0]);
                        a2[q][1] = fma2(ss, m1, a2[q][1]);
                        a2[q][2] = fma2(ss, m2, a2[q][2]);
                        a2[q][3] = fma2(ss, m3, a2[q][3]);
                    }
                }
            }
#pragma unroll
            for (int q = 0; q < 4; q++) {
                float v[8];
                unpack2(a2[q][0], v[0], v[1]); unpack2(a2[q][1], v[2], v[3]);
                unpack2(a2[q][2], v[4], v[5]); unpack2(a2[q][3], v[6], v[7]);
                float* dst = &g_part[js*2 + kh][b*Nn + ti*4 + q][d0];
                *(float4*)dst       = make_float4(v[0],v[1],v[2],v[3]);
                *(float4*)(dst + 4) = make_float4(v[4],v[5],v[6],v[7]);
            }
            cluster_bar();
        }
    }
}

extern "C" void kernel_launch(void* const* d_in, const int* in_sizes, int n_in,
                              void* d_out, int out_size) {
    const float* inputs = (const float*)d_in[0];
    const int*   mask   = (const int*)  d_in[1];
    const float* We     = (const float*)d_in[2];
    const float* be     = (const float*)d_in[3];
    const float* Wa     = (const float*)d_in[4];
    const float* ba     = (const float*)d_in[5];
    const float* Wr     = (const float*)d_in[6];
    const float* br     = (const float*)d_in[7];
    const float* Wz     = (const float*)d_in[8];
    const float* bz     = (const float*)d_in[9];
    const float* Wh     = (const float*)d_in[10];
    const float* bh     = (const float*)d_in[11];
    float* out = (float*)d_out;

    static int configured = 0;
    if (!configured) {
        cudaFuncSetAttribute(grrn, cudaFuncAttributeMaxDynamicSharedMemorySize,
                             SMEM_FLOATS * 4);
        configured = 1;
    }
    grrn<<<GRID, THREADS, SMEM_FLOATS * 4>>>(inputs, mask, We, be, Wa, ba,
                                             Wr, br, Wz, bz, Wh, bh, out);
}